// round 3
// baseline (speedup 1.0000x reference)
#include <cuda_runtime.h>
#include <cuda_bf16.h>
#include <cstdint>

// ---------------------------------------------------------------------------
// Problem constants
// ---------------------------------------------------------------------------
#define L_SP 9
#define BATCH 256
// Ns = 5023, 1256, 314, 79, 20 ; Cs = 3, 32, 64, 128, 256 ; latent = 128

// ---------------------------------------------------------------------------
// Scratch (device globals; no allocation allowed)
// ---------------------------------------------------------------------------
__device__ float g_buf[92602368];   // gathered spiral rows (max 321536*288)
__device__ float a_buf[41148416];   // conv outputs h_i     (max 5023*256*32)
__device__ float y_buf[10289152];   // pooled outputs y_i   (max 1256*256*32)

// ---------------------------------------------------------------------------
// Generic SGEMM: C = act(A(MxK,row) * B(KxN,row) + bias)
// BM=128, BK=8, TM=8; BN/TN templated, 256 threads.
// ---------------------------------------------------------------------------
template <int BN, int TN>
__global__ __launch_bounds__(256) void sgemm_kernel(
    int M, int N, int K,
    const float* __restrict__ A, const float* __restrict__ B,
    float* __restrict__ C, const float* __restrict__ bias, int act)
{
    constexpr int BM = 128, BK = 8, TM = 8;
    constexpr int NTX = BN / TN;           // 16
    __shared__ float As[BK][BM];
    __shared__ float Bs[BK][BN];

    const int tid = threadIdx.x;
    const int tx = tid % NTX;
    const int ty = tid / NTX;              // 0..15
    const int row0 = blockIdx.y * BM;
    const int col0 = blockIdx.x * BN;

    float acc[TM][TN];
#pragma unroll
    for (int i = 0; i < TM; i++)
#pragma unroll
        for (int j = 0; j < TN; j++) acc[i][j] = 0.f;

    constexpr int ALOADS = BM * BK / 256;  // 4
    constexpr int BLOADS = BK * BN / 256;

    for (int k0 = 0; k0 < K; k0 += BK) {
#pragma unroll
        for (int i = 0; i < ALOADS; i++) {
            int lin = tid + i * 256;
            int kk = lin % BK, mm = lin / BK;
            int gm = row0 + mm, gk = k0 + kk;
            As[kk][mm] = (gm < M && gk < K) ? A[(long long)gm * K + gk] : 0.f;
        }
#pragma unroll
        for (int i = 0; i < BLOADS; i++) {
            int lin = tid + i * 256;
            int nn = lin % BN, kk = lin / BN;
            int gn = col0 + nn, gk = k0 + kk;
            Bs[kk][nn] = (gn < N && gk < K) ? B[(long long)gk * N + gn] : 0.f;
        }
        __syncthreads();
#pragma unroll
        for (int kk = 0; kk < BK; kk++) {
            float a[TM], bv[TN];
#pragma unroll
            for (int i = 0; i < TM; i++) a[i] = As[kk][ty * TM + i];
#pragma unroll
            for (int j = 0; j < TN; j++) bv[j] = Bs[kk][tx * TN + j];
#pragma unroll
            for (int i = 0; i < TM; i++)
#pragma unroll
                for (int j = 0; j < TN; j++) acc[i][j] += a[i] * bv[j];
        }
        __syncthreads();
    }

#pragma unroll
    for (int i = 0; i < TM; i++) {
        int gm = row0 + ty * TM + i;
        if (gm >= M) continue;
#pragma unroll
        for (int j = 0; j < TN; j++) {
            int gn = col0 + tx * TN + j;
            if (gn >= N) continue;
            float v = acc[i][j];
            if (bias) v += bias[gn];
            if (act) v = (v > 0.f) ? v : expm1f(v);
            C[(long long)gm * N + gn] = v;
        }
    }
}

// ---------------------------------------------------------------------------
// Stage-0 fused spiral conv: one warp per output row (n,b).
// x: (B,5023,3) ; idx: (5023,9) ; W: (27,32) ; h out: (5023,256,32)
// ---------------------------------------------------------------------------
__global__ __launch_bounds__(256) void conv0_kernel(
    const float* __restrict__ x, const int* __restrict__ idx,
    const float* __restrict__ W, const float* __restrict__ bias,
    float* __restrict__ h)
{
    __shared__ float Ws[27 * 32];
    __shared__ float bs[32];
    const int tid = threadIdx.x;
    for (int i = tid; i < 27 * 32; i += 256) Ws[i] = W[i];
    if (tid < 32) bs[tid] = bias[tid];
    __syncthreads();

    const int warp = tid >> 5, lane = tid & 31;
    const long long row = (long long)blockIdx.x * 8 + warp;  // n*256 + b
    const int n = (int)(row >> 8);
    const int b = (int)(row & 255);

    float gval = 0.f;
    if (lane < 27) {
        int l = lane / 3, c = lane - l * 3;
        int node = idx[n * L_SP + l];
        gval = x[(long long)b * (5023 * 3) + node * 3 + c];
    }
    float acc = bs[lane];
#pragma unroll
    for (int k = 0; k < 27; k++) {
        float a = __shfl_sync(0xffffffffu, gval, k);
        acc += a * Ws[k * 32 + lane];
    }
    acc = (acc > 0.f) ? acc : expm1f(acc);
    h[row * 32 + lane] = acc;
}

// ---------------------------------------------------------------------------
// Vectorized gather (float4): C divisible by 4.
// out[((n*B+b)*L + l)*C + c] = in[idx[n,l]*(B*C) + b*C + c]
// One thread per float4; linear index over (n,b,l,c4).
// ---------------------------------------------------------------------------
__global__ __launch_bounds__(256) void gather4_kernel(
    const float4* __restrict__ in, const int* __restrict__ idx,
    float4* __restrict__ out, int C4, long long total4)
{
    long long i = (long long)blockIdx.x * blockDim.x + threadIdx.x;
    if (i >= total4) return;
    int c4 = (int)(i % C4);
    long long t = i / C4;
    int l = (int)(t % L_SP); t /= L_SP;
    int b = (int)(t % BATCH);
    int n = (int)(t / BATCH);
    long long src = ((long long)idx[n * L_SP + l] * BATCH + b) * C4 + c4;
    out[i] = in[src];
}

// ---------------------------------------------------------------------------
// Final FC: out[b,l] = sum_{n,c} y3[n*65536 + b*256 + c] * Wfc[(n*256+c)*128 + l]
// ---------------------------------------------------------------------------
__global__ __launch_bounds__(128) void fc_kernel(
    const float* __restrict__ h, const float* __restrict__ W,
    const float* __restrict__ bias, float* __restrict__ out)
{
    __shared__ float s[5120];
    const int b = blockIdx.x;
    for (int k = threadIdx.x; k < 5120; k += 128) {
        int n = k >> 8, c = k & 255;
        s[k] = h[n * 65536 + b * 256 + c];
    }
    __syncthreads();
    float acc = bias[threadIdx.x];
#pragma unroll 8
    for (int k = 0; k < 5120; k++)
        acc += s[k] * W[k * 128 + threadIdx.x];
    out[b * 128 + threadIdx.x] = acc;
}

// ---------------------------------------------------------------------------
// Launch helpers
// ---------------------------------------------------------------------------
static inline void launch_sgemm128(int M, int N, int K, const float* A, const float* B,
                                   float* C, const float* bias, int act)
{
    dim3 grid((N + 127) / 128, (M + 127) / 128);
    sgemm_kernel<128, 8><<<grid, 256>>>(M, N, K, A, B, C, bias, act);
}
static inline void launch_sgemm64(int M, int N, int K, const float* A, const float* B,
                                  float* C, const float* bias, int act)
{
    dim3 grid((N + 63) / 64, (M + 127) / 128);
    sgemm_kernel<64, 4><<<grid, 256>>>(M, N, K, A, B, C, bias, act);
}
static inline void launch_gather(const float* in, const int* idx, float* out, int N, int C)
{
    long long total4 = (long long)N * BATCH * L_SP * (C / 4);
    int blocks = (int)((total4 + 255) / 256);
    gather4_kernel<<<blocks, 256>>>((const float4*)in, idx, (float4*)out, C / 4, total4);
}

// ---------------------------------------------------------------------------
// kernel_launch — inputs bound BY ELEMENT COUNT (robust to metadata ordering).
// All sizes unique except b2 & bfc (both 128); b2 precedes bfc in any
// plausible ordering (signature or dict-insertion), so 1st 128-sized = b2.
// ---------------------------------------------------------------------------
extern "C" void kernel_launch(void* const* d_in, const int* in_sizes, int n_in,
                              void* d_out, int out_size)
{
    const void* x = 0; const void* idx0 = 0; const void* idx1 = 0;
    const void* idx2 = 0; const void* idx3 = 0;
    const void* D0 = 0; const void* D1 = 0; const void* D2 = 0; const void* D3 = 0;
    const void* W0 = 0; const void* b0 = 0; const void* W1 = 0; const void* b1 = 0;
    const void* W2 = 0; const void* b2 = 0; const void* W3 = 0; const void* b3 = 0;
    const void* Wfc = 0; const void* bfc = 0;

    for (int i = 0; i < n_in; i++) {
        const void* p = d_in[i];
        switch (in_sizes[i]) {
            case 3857664: x    = p; break;   // 256*5023*3
            case 45207:   idx0 = p; break;   // 5023*9
            case 11304:   idx1 = p; break;   // 1256*9
            case 2826:    idx2 = p; break;   // 314*9
            case 711:     idx3 = p; break;   // 79*9
            case 6308888: D0   = p; break;   // 1256*5023
            case 394384:  D1   = p; break;   // 314*1256
            case 24806:   D2   = p; break;   // 79*314
            case 1580:    D3   = p; break;   // 20*79
            case 864:     W0   = p; break;   // 27*32
            case 32:      b0   = p; break;
            case 18432:   W1   = p; break;   // 288*64
            case 64:      b1   = p; break;
            case 73728:   W2   = p; break;   // 576*128
            case 294912:  W3   = p; break;   // 1152*256
            case 256:     b3   = p; break;
            case 655360:  Wfc  = p; break;   // 5120*128
            case 128:     if (!b2) b2 = p; else bfc = p; break;
            default: break;
        }
    }

    float* out = (float*)d_out;
    float* gb; cudaGetSymbolAddress((void**)&gb, g_buf);
    float* ab; cudaGetSymbolAddress((void**)&ab, a_buf);
    float* yb; cudaGetSymbolAddress((void**)&yb, y_buf);

    // ---- Block 0: fused spiral conv, h0 layout (n=5023, b=256, c=32)
    conv0_kernel<<<(5023 * 256) / 8, 256>>>((const float*)x, (const int*)idx0,
                                            (const float*)W0, (const float*)b0, ab);
    // y0 = D0 @ h0 : (1256 x 5023) @ (5023 x 8192)
    launch_sgemm128(1256, 256 * 32, 5023, (const float*)D0, ab, yb, nullptr, 0);

    // ---- Block 1
    launch_gather(yb, (const int*)idx1, gb, 1256, 32);
    launch_sgemm64(1256 * 256, 64, 288, gb, (const float*)W1, ab, (const float*)b1, 1);
    launch_sgemm128(314, 256 * 64, 1256, (const float*)D1, ab, yb, nullptr, 0);

    // ---- Block 2
    launch_gather(yb, (const int*)idx2, gb, 314, 64);
    launch_sgemm128(314 * 256, 128, 576, gb, (const float*)W2, ab, (const float*)b2, 1);
    launch_sgemm128(79, 256 * 128, 314, (const float*)D2, ab, yb, nullptr, 0);

    // ---- Block 3
    launch_gather(yb, (const int*)idx3, gb, 79, 128);
    launch_sgemm128(79 * 256, 256, 1152, gb, (const float*)W3, ab, (const float*)b3, 1);
    launch_sgemm128(20, 256 * 256, 79, (const float*)D3, ab, yb, nullptr, 0);

    // ---- Final FC: (256 x 5120) @ (5120 x 128)
    fc_kernel<<<256, 128>>>(yb, (const float*)Wfc, (const float*)bfc, out);
}

// round 5
// speedup vs baseline: 1.4928x; 1.4928x over previous
#include <cuda_runtime.h>
#include <cuda_bf16.h>
#include <cstdint>

#define L_SP 9
#define BATCH 256
// Ns = 5023, 1256, 314, 79, 20 ; Cs = 3, 32, 64, 128, 256 ; latent = 128

// ---------------------------------------------------------------------------
// Scratch (device globals; no allocation allowed)
// ---------------------------------------------------------------------------
__device__ float g_buf[92602368];   // gathered spiral rows (max 321536*288)
__device__ float a_buf[41148416];   // conv outputs h_i     (max 5023*256*32)
__device__ float y_buf[10289152];   // pooled outputs y_i   (max 1256*256*32)

// ---------------------------------------------------------------------------
// Double-buffered SGEMM: C = act(A(MxK,row) * B(KxN,row) + bias)
// Requirements: N % BN == 0 (always true here), (BM/TM)*(BN/TN) == 256,
// BK % 4 == 0. M and K arbitrary (predicated).
// AK4: A rows are 16B-aligned (K % 4 == 0) -> vector loads; else scalar.
// ---------------------------------------------------------------------------
template <int BM, int BN, int BK, int TM, int TN, bool AK4>
__global__ __launch_bounds__(256) void sgemm_db(
    int M, int N, int K,
    const float* __restrict__ A, const float* __restrict__ B,
    float* __restrict__ C, const float* __restrict__ bias, int act)
{
    constexpr int PAD = 4;
    constexpr int NTX = BN / TN;
    constexpr int NTY = BM / TM;
    static_assert(NTX * NTY == 256, "thread shape");
    static_assert(BK % 4 == 0, "BK%4");

    __shared__ float As[2][BK][BM + PAD];
    __shared__ float Bs[2][BK][BN];

    const int tid = threadIdx.x;
    const int tx = tid % NTX;
    const int ty = tid / NTX;
    const int row0 = blockIdx.y * BM;
    const int col0 = blockIdx.x * BN;

    // A: BM*BK floats, each thread handles 4 consecutive floats along K.
    constexpr int KV = BK / 4;
    constexpr int A_V4 = BM * BK / 4;
    constexpr int A_IT = (A_V4 + 255) / 256;
    // B: BK*BN floats as float4 along N.
    constexpr int NV = BN / 4;
    constexpr int B_V4 = BK * BN / 4;
    constexpr int B_IT = (B_V4 + 255) / 256;

    float4 aReg[A_IT], bReg[B_IT];
    float acc[TM][TN] = {};

    const int ktiles = (K + BK - 1) / BK;

    auto loadTile = [&](int t) {
#pragma unroll
        for (int i = 0; i < A_IT; i++) {
            int lin = tid + i * 256;
            float4 v = make_float4(0.f, 0.f, 0.f, 0.f);
            bool ok = (A_V4 % 256 == 0) || (lin < A_V4);
            if (ok) {
                int m = lin / KV;
                int gk = t * BK + (lin % KV) * 4;
                int gm = row0 + m;
                if (gm < M) {
                    const float* ap = &A[(long long)gm * K];
                    if (AK4 && gk + 3 < K) {
                        v = *(const float4*)&ap[gk];
                    } else {
                        if (gk + 0 < K) v.x = ap[gk + 0];
                        if (gk + 1 < K) v.y = ap[gk + 1];
                        if (gk + 2 < K) v.z = ap[gk + 2];
                        if (gk + 3 < K) v.w = ap[gk + 3];
                    }
                }
            }
            aReg[i] = v;
        }
#pragma unroll
        for (int i = 0; i < B_IT; i++) {
            int lin = tid + i * 256;
            float4 v = make_float4(0.f, 0.f, 0.f, 0.f);
            bool ok = (B_V4 % 256 == 0) || (lin < B_V4);
            if (ok) {
                int k = lin / NV;
                int gk = t * BK + k;
                int gn = col0 + (lin % NV) * 4;
                if (gk < K) v = *(const float4*)&B[(long long)gk * N + gn];
            }
            bReg[i] = v;
        }
    };

    auto storeTile = [&](int buf) {
#pragma unroll
        for (int i = 0; i < A_IT; i++) {
            int lin = tid + i * 256;
            if ((A_V4 % 256 == 0) || (lin < A_V4)) {
                int m = lin / KV;
                int k4 = (lin % KV) * 4;
                As[buf][k4 + 0][m] = aReg[i].x;
                As[buf][k4 + 1][m] = aReg[i].y;
                As[buf][k4 + 2][m] = aReg[i].z;
                As[buf][k4 + 3][m] = aReg[i].w;
            }
        }
#pragma unroll
        for (int i = 0; i < B_IT; i++) {
            int lin = tid + i * 256;
            if ((B_V4 % 256 == 0) || (lin < B_V4)) {
                int k = lin / NV;
                int n4 = (lin % NV) * 4;
                *(float4*)&Bs[buf][k][n4] = bReg[i];
            }
        }
    };

    loadTile(0);
    storeTile(0);
    __syncthreads();

    int buf = 0;
    for (int t = 0; t < ktiles; t++) {
        if (t + 1 < ktiles) loadTile(t + 1);
#pragma unroll
        for (int kk = 0; kk < BK; kk++) {
            float a[TM], b[TN];
            if constexpr (TM % 4 == 0) {
#pragma unroll
                for (int i = 0; i < TM; i += 4)
                    *(float4*)&a[i] = *(const float4*)&As[buf][kk][ty * TM + i];
            } else {
#pragma unroll
                for (int i = 0; i < TM; i++) a[i] = As[buf][kk][ty * TM + i];
            }
            if constexpr (TN % 4 == 0) {
#pragma unroll
                for (int j = 0; j < TN; j += 4)
                    *(float4*)&b[j] = *(const float4*)&Bs[buf][kk][tx * TN + j];
            } else {
#pragma unroll
                for (int j = 0; j < TN; j++) b[j] = Bs[buf][kk][tx * TN + j];
            }
#pragma unroll
            for (int i = 0; i < TM; i++)
#pragma unroll
                for (int j = 0; j < TN; j++)
                    acc[i][j] += a[i] * b[j];
        }
        if (t + 1 < ktiles) {
            storeTile(buf ^ 1);
            __syncthreads();
            buf ^= 1;
        }
    }

#pragma unroll
    for (int i = 0; i < TM; i++) {
        int gm = row0 + ty * TM + i;
        if (gm >= M) continue;
#pragma unroll
        for (int j = 0; j < TN; j++) {
            int gn = col0 + tx * TN + j;
            float v = acc[i][j];
            if (bias) v += bias[gn];
            if (act) v = (v > 0.f) ? v : expm1f(v);
            C[(long long)gm * N + gn] = v;
        }
    }
}

// ---------------------------------------------------------------------------
// Stage-0 fused spiral conv: one warp per output row (n,b).
// x: (B,5023,3) ; idx: (5023,9) ; W: (27,32) ; h out: (5023,256,32)
// ---------------------------------------------------------------------------
__global__ __launch_bounds__(256) void conv0_kernel(
    const float* __restrict__ x, const int* __restrict__ idx,
    const float* __restrict__ W, const float* __restrict__ bias,
    float* __restrict__ h)
{
    __shared__ float Ws[27 * 32];
    __shared__ float bs[32];
    const int tid = threadIdx.x;
    for (int i = tid; i < 27 * 32; i += 256) Ws[i] = W[i];
    if (tid < 32) bs[tid] = bias[tid];
    __syncthreads();

    const int warp = tid >> 5, lane = tid & 31;
    const long long row = (long long)blockIdx.x * 8 + warp;  // n*256 + b
    const int n = (int)(row >> 8);
    const int b = (int)(row & 255);

    float gval = 0.f;
    if (lane < 27) {
        int l = lane / 3, c = lane - l * 3;
        int node = idx[n * L_SP + l];
        gval = x[(long long)b * (5023 * 3) + node * 3 + c];
    }
    float acc = bs[lane];
#pragma unroll
    for (int k = 0; k < 27; k++) {
        float a = __shfl_sync(0xffffffffu, gval, k);
        acc += a * Ws[k * 32 + lane];
    }
    acc = (acc > 0.f) ? acc : expm1f(acc);
    h[row * 32 + lane] = acc;
}

// ---------------------------------------------------------------------------
// Vectorized gather (float4): out[((n*B+b)*L+l)*C+c] = in[(idx[n,l]*B+b)*C+c]
// ---------------------------------------------------------------------------
__global__ __launch_bounds__(256) void gather4_kernel(
    const float4* __restrict__ in, const int* __restrict__ idx,
    float4* __restrict__ out, int C4, long long total4)
{
    long long i = (long long)blockIdx.x * blockDim.x + threadIdx.x;
    if (i >= total4) return;
    int c4 = (int)(i % C4);
    long long t = i / C4;
    int l = (int)(t % L_SP); t /= L_SP;
    int b = (int)(t % BATCH);
    int n = (int)(t / BATCH);
    long long src = ((long long)idx[n * L_SP + l] * BATCH + b) * C4 + c4;
    out[i] = in[src];
}

// ---------------------------------------------------------------------------
// Final FC: out[b,l] = sum_{n,c} y3[n*65536 + b*256 + c] * Wfc[(n*256+c)*128 + l]
// ---------------------------------------------------------------------------
__global__ __launch_bounds__(128) void fc_kernel(
    const float* __restrict__ h, const float* __restrict__ W,
    const float* __restrict__ bias, float* __restrict__ out)
{
    __shared__ float s[5120];
    const int b = blockIdx.x;
    for (int k = threadIdx.x; k < 5120; k += 128) {
        int n = k >> 8, c = k & 255;
        s[k] = h[n * 65536 + b * 256 + c];
    }
    __syncthreads();
    float acc = bias[threadIdx.x];
#pragma unroll 8
    for (int k = 0; k < 5120; k++)
        acc += s[k] * W[k * 128 + threadIdx.x];
    out[b * 128 + threadIdx.x] = acc;
}

// ---------------------------------------------------------------------------
// Launch helpers (dispatch on K alignment)
// ---------------------------------------------------------------------------
static inline void gemm_big(int M, int N, int K, const float* A, const float* B,
                            float* C, const float* bias, int act)
{
    dim3 grid(N / 128, (M + 127) / 128);
    if (K % 4 == 0)
        sgemm_db<128, 128, 16, 8, 8, true><<<grid, 256>>>(M, N, K, A, B, C, bias, act);
    else
        sgemm_db<128, 128, 16, 8, 8, false><<<grid, 256>>>(M, N, K, A, B, C, bias, act);
}
static inline void gemm_n64(int M, int N, int K, const float* A, const float* B,
                            float* C, const float* bias, int act)
{
    dim3 grid(N / 64, (M + 127) / 128);
    if (K % 4 == 0)
        sgemm_db<128, 64, 16, 8, 4, true><<<grid, 256>>>(M, N, K, A, B, C, bias, act);
    else
        sgemm_db<128, 64, 16, 8, 4, false><<<grid, 256>>>(M, N, K, A, B, C, bias, act);
}
static inline void gemm_m32(int M, int N, int K, const float* A, const float* B,
                            float* C, const float* bias, int act)
{
    dim3 grid(N / 128, (M + 31) / 32);
    if (K % 4 == 0)
        sgemm_db<32, 128, 16, 2, 8, true><<<grid, 256>>>(M, N, K, A, B, C, bias, act);
    else
        sgemm_db<32, 128, 16, 2, 8, false><<<grid, 256>>>(M, N, K, A, B, C, bias, act);
}
static inline void launch_gather(const float* in, const int* idx, float* out, int N, int C)
{
    long long total4 = (long long)N * BATCH * L_SP * (C / 4);
    int blocks = (int)((total4 + 255) / 256);
    gather4_kernel<<<blocks, 256>>>((const float4*)in, idx, (float4*)out, C / 4, total4);
}

// ---------------------------------------------------------------------------
// kernel_launch — inputs bound BY ELEMENT COUNT (robust to metadata ordering).
// All sizes unique except b2 & bfc (both 128); b2 precedes bfc, so the first
// 128-sized input is b2.
// ---------------------------------------------------------------------------
extern "C" void kernel_launch(void* const* d_in, const int* in_sizes, int n_in,
                              void* d_out, int out_size)
{
    const void* x = 0; const void* idx0 = 0; const void* idx1 = 0;
    const void* idx2 = 0; const void* idx3 = 0;
    const void* D0 = 0; const void* D1 = 0; const void* D2 = 0; const void* D3 = 0;
    const void* W0 = 0; const void* b0 = 0; const void* W1 = 0; const void* b1 = 0;
    const void* W2 = 0; const void* b2 = 0; const void* W3 = 0; const void* b3 = 0;
    const void* Wfc = 0; const void* bfc = 0;

    for (int i = 0; i < n_in; i++) {
        const void* p = d_in[i];
        switch (in_sizes[i]) {
            case 3857664: x    = p; break;   // 256*5023*3
            case 45207:   idx0 = p; break;   // 5023*9
            case 11304:   idx1 = p; break;   // 1256*9
            case 2826:    idx2 = p; break;   // 314*9
            case 711:     idx3 = p; break;   // 79*9
            case 6308888: D0   = p; break;   // 1256*5023
            case 394384:  D1   = p; break;   // 314*1256
            case 24806:   D2   = p; break;   // 79*314
            case 1580:    D3   = p; break;   // 20*79
            case 864:     W0   = p; break;   // 27*32
            case 32:      b0   = p; break;
            case 18432:   W1   = p; break;   // 288*64
            case 64:      b1   = p; break;
            case 73728:   W2   = p; break;   // 576*128
            case 294912:  W3   = p; break;   // 1152*256
            case 256:     b3   = p; break;
            case 655360:  Wfc  = p; break;   // 5120*128
            case 128:     if (!b2) b2 = p; else bfc = p; break;
            default: break;
        }
    }

    float* out = (float*)d_out;
    float* gb; cudaGetSymbolAddress((void**)&gb, g_buf);
    float* ab; cudaGetSymbolAddress((void**)&ab, a_buf);
    float* yb; cudaGetSymbolAddress((void**)&yb, y_buf);

    // ---- Block 0: fused spiral conv, h0 layout (n=5023, b=256, c=32)
    conv0_kernel<<<(5023 * 256) / 8, 256>>>((const float*)x, (const int*)idx0,
                                            (const float*)W0, (const float*)b0, ab);
    // y0 = D0 @ h0 : (1256 x 5023) @ (5023 x 8192)   [K=5023 -> scalar A]
    gemm_big(1256, 256 * 32, 5023, (const float*)D0, ab, yb, nullptr, 0);

    // ---- Block 1
    launch_gather(yb, (const int*)idx1, gb, 1256, 32);
    gemm_n64(1256 * 256, 64, 288, gb, (const float*)W1, ab, (const float*)b1, 1);
    gemm_big(314, 256 * 64, 1256, (const float*)D1, ab, yb, nullptr, 0);

    // ---- Block 2
    launch_gather(yb, (const int*)idx2, gb, 314, 64);
    gemm_big(314 * 256, 128, 576, gb, (const float*)W2, ab, (const float*)b2, 1);
    gemm_m32(79, 256 * 128, 314, (const float*)D2, ab, yb, nullptr, 0);   // K=314 -> scalar A

    // ---- Block 3
    launch_gather(yb, (const int*)idx3, gb, 79, 128);
    gemm_big(79 * 256, 256, 1152, gb, (const float*)W3, ab, (const float*)b3, 1);
    gemm_m32(20, 256 * 256, 79, (const float*)D3, ab, yb, nullptr, 0);    // K=79 -> scalar A

    // ---- Final FC: (256 x 5120) @ (5120 x 128)
    fc_kernel<<<256, 128>>>(yb, (const float*)Wfc, (const float*)bfc, out);
}

// round 7
// speedup vs baseline: 3.1414x; 2.1044x over previous
#include <cuda_runtime.h>
#include <cuda_bf16.h>
#include <cstdint>

#define L_SP 9
#define BATCH 256
// Ns = 5023, 1256, 314, 79, 20 ; Cs = 3, 32, 64, 128, 256 ; latent = 128

// ---------------------------------------------------------------------------
// Scratch (device globals; no allocation allowed)
// ---------------------------------------------------------------------------
__device__ float g_buf[92602368];   // gathered spiral rows (max 321536*288)
__device__ float a_buf[41148416];   // conv outputs h_i     (max 5023*256*32)
__device__ float y_buf[10289152];   // pooled outputs y_i   (max 1256*256*32)

__device__ __forceinline__ float f2tf32(float f) {
    uint32_t r;
    asm("cvt.rna.tf32.f32 %0, %1;" : "=r"(r) : "f"(f));
    return __uint_as_float(r);
}

// ---------------------------------------------------------------------------
// tf32 tensor-core GEMM: C = act(A(MxK,row) * B(KxN,row) + bias)
// Double-buffered smem, mma.sync m16n8k8. 256 threads = 8 warps.
// (BM/WM)*(BN/WN)==8. N % BN == 0 required (true for all shapes here).
// M, K arbitrary. AK4: K % 4 == 0 -> vectorized A loads.
// ---------------------------------------------------------------------------
template <int BM, int BN, int BK, int WM, int WN, bool AK4>
__global__ __launch_bounds__(256) void sgemm_tc(
    int M, int N, int K,
    const float* __restrict__ A, const float* __restrict__ B,
    float* __restrict__ C, const float* __restrict__ bias, int act)
{
    constexpr int PAD = 8;
    constexpr int NWN = BN / WN;
    constexpr int NWM = BM / WM;
    static_assert(NWM * NWN == 8, "8 warps");
    static_assert(BK % 8 == 0, "BK%8");
    constexpr int MT = WM / 16;
    constexpr int NT = WN / 8;

    __shared__ float As[2][BK][BM + PAD];
    __shared__ float Bs[2][BK][BN + PAD];

    const int tid = threadIdx.x;
    const int warp = tid >> 5;
    const int lane = tid & 31;
    const int g = lane >> 2;        // groupID
    const int tig = lane & 3;       // thread-in-group
    const int wn0 = (warp % NWN) * WN;
    const int wm0 = (warp / NWN) * WM;
    const int row0 = blockIdx.y * BM;
    const int col0 = blockIdx.x * BN;

    constexpr int KV = BK / 4;
    constexpr int A_V4 = BM * BK / 4;
    constexpr int A_IT = (A_V4 + 255) / 256;
    constexpr int NV = BN / 4;
    constexpr int B_V4 = BK * BN / 4;
    constexpr int B_IT = (B_V4 + 255) / 256;

    float4 aReg[A_IT], bReg[B_IT];
    float acc[MT][NT][4];
#pragma unroll
    for (int i = 0; i < MT; i++)
#pragma unroll
        for (int j = 0; j < NT; j++)
#pragma unroll
            for (int v = 0; v < 4; v++) acc[i][j][v] = 0.f;

    const int ktiles = (K + BK - 1) / BK;

    auto loadTile = [&](int t) {
#pragma unroll
        for (int i = 0; i < A_IT; i++) {
            int lin = tid + i * 256;
            float4 v = make_float4(0.f, 0.f, 0.f, 0.f);
            bool ok = (A_V4 % 256 == 0) || (lin < A_V4);
            if (ok) {
                int m = lin / KV;
                int gk = t * BK + (lin % KV) * 4;
                int gm = row0 + m;
                if (gm < M) {
                    const float* ap = &A[(long long)gm * K];
                    if (AK4 && gk + 3 < K) {
                        v = *(const float4*)&ap[gk];
                    } else {
                        if (gk + 0 < K) v.x = ap[gk + 0];
                        if (gk + 1 < K) v.y = ap[gk + 1];
                        if (gk + 2 < K) v.z = ap[gk + 2];
                        if (gk + 3 < K) v.w = ap[gk + 3];
                    }
                }
            }
            aReg[i] = v;
        }
#pragma unroll
        for (int i = 0; i < B_IT; i++) {
            int lin = tid + i * 256;
            float4 v = make_float4(0.f, 0.f, 0.f, 0.f);
            bool ok = (B_V4 % 256 == 0) || (lin < B_V4);
            if (ok) {
                int k = lin / NV;
                int gk = t * BK + k;
                int gn = col0 + (lin % NV) * 4;
                if (gk < K) v = *(const float4*)&B[(long long)gk * N + gn];
            }
            bReg[i] = v;
        }
    };

    auto storeTile = [&](int buf) {
#pragma unroll
        for (int i = 0; i < A_IT; i++) {
            int lin = tid + i * 256;
            if ((A_V4 % 256 == 0) || (lin < A_V4)) {
                int m = lin / KV;
                int k4 = (lin % KV) * 4;
                As[buf][k4 + 0][m] = f2tf32(aReg[i].x);
                As[buf][k4 + 1][m] = f2tf32(aReg[i].y);
                As[buf][k4 + 2][m] = f2tf32(aReg[i].z);
                As[buf][k4 + 3][m] = f2tf32(aReg[i].w);
            }
        }
#pragma unroll
        for (int i = 0; i < B_IT; i++) {
            int lin = tid + i * 256;
            if ((B_V4 % 256 == 0) || (lin < B_V4)) {
                int k = lin / NV;
                int n4 = (lin % NV) * 4;
                Bs[buf][k][n4 + 0] = f2tf32(bReg[i].x);
                Bs[buf][k][n4 + 1] = f2tf32(bReg[i].y);
                Bs[buf][k][n4 + 2] = f2tf32(bReg[i].z);
                Bs[buf][k][n4 + 3] = f2tf32(bReg[i].w);
            }
        }
    };

    loadTile(0);
    storeTile(0);
    __syncthreads();

    int buf = 0;
    for (int t = 0; t < ktiles; t++) {
        if (t + 1 < ktiles) loadTile(t + 1);
#pragma unroll
        for (int kt = 0; kt < BK / 8; kt++) {
            uint32_t af[MT][4], bf[NT][2];
#pragma unroll
            for (int mt = 0; mt < MT; mt++) {
                int m = wm0 + mt * 16 + g;
                af[mt][0] = __float_as_uint(As[buf][kt * 8 + tig    ][m]);
                af[mt][1] = __float_as_uint(As[buf][kt * 8 + tig    ][m + 8]);
                af[mt][2] = __float_as_uint(As[buf][kt * 8 + tig + 4][m]);
                af[mt][3] = __float_as_uint(As[buf][kt * 8 + tig + 4][m + 8]);
            }
#pragma unroll
            for (int nt = 0; nt < NT; nt++) {
                int n = wn0 + nt * 8 + g;
                bf[nt][0] = __float_as_uint(Bs[buf][kt * 8 + tig    ][n]);
                bf[nt][1] = __float_as_uint(Bs[buf][kt * 8 + tig + 4][n]);
            }
#pragma unroll
            for (int mt = 0; mt < MT; mt++)
#pragma unroll
                for (int nt = 0; nt < NT; nt++) {
                    asm volatile(
                        "mma.sync.aligned.m16n8k8.row.col.f32.tf32.tf32.f32 "
                        "{%0,%1,%2,%3}, {%4,%5,%6,%7}, {%8,%9}, {%0,%1,%2,%3};"
                        : "+f"(acc[mt][nt][0]), "+f"(acc[mt][nt][1]),
                          "+f"(acc[mt][nt][2]), "+f"(acc[mt][nt][3])
                        : "r"(af[mt][0]), "r"(af[mt][1]), "r"(af[mt][2]), "r"(af[mt][3]),
                          "r"(bf[nt][0]), "r"(bf[nt][1]));
                }
        }
        if (t + 1 < ktiles) {
            storeTile(buf ^ 1);
            __syncthreads();
            buf ^= 1;
        }
    }

    // Epilogue: c0,c1 -> (row=g, col=2*tig,2*tig+1); c2,c3 -> row+8.
#pragma unroll
    for (int mt = 0; mt < MT; mt++) {
#pragma unroll
        for (int nt = 0; nt < NT; nt++) {
            int gn = col0 + wn0 + nt * 8 + 2 * tig;
            float bv0 = bias ? bias[gn] : 0.f;
            float bv1 = bias ? bias[gn + 1] : 0.f;
            int r0 = row0 + wm0 + mt * 16 + g;
            int r1 = r0 + 8;
            if (r0 < M) {
                float v0 = acc[mt][nt][0] + bv0;
                float v1 = acc[mt][nt][1] + bv1;
                if (act) {
                    v0 = (v0 > 0.f) ? v0 : expm1f(v0);
                    v1 = (v1 > 0.f) ? v1 : expm1f(v1);
                }
                *(float2*)&C[(long long)r0 * N + gn] = make_float2(v0, v1);
            }
            if (r1 < M) {
                float v0 = acc[mt][nt][2] + bv0;
                float v1 = acc[mt][nt][3] + bv1;
                if (act) {
                    v0 = (v0 > 0.f) ? v0 : expm1f(v0);
                    v1 = (v1 > 0.f) ? v1 : expm1f(v1);
                }
                *(float2*)&C[(long long)r1 * N + gn] = make_float2(v0, v1);
            }
        }
    }
}

// ---------------------------------------------------------------------------
// Stage-0 fused spiral conv: one warp per output row (n,b).
// ---------------------------------------------------------------------------
__global__ __launch_bounds__(256) void conv0_kernel(
    const float* __restrict__ x, const int* __restrict__ idx,
    const float* __restrict__ W, const float* __restrict__ bias,
    float* __restrict__ h)
{
    __shared__ float Ws[27 * 32];
    __shared__ float bs[32];
    const int tid = threadIdx.x;
    for (int i = tid; i < 27 * 32; i += 256) Ws[i] = W[i];
    if (tid < 32) bs[tid] = bias[tid];
    __syncthreads();

    const int warp = tid >> 5, lane = tid & 31;
    const long long row = (long long)blockIdx.x * 8 + warp;  // n*256 + b
    const int n = (int)(row >> 8);
    const int b = (int)(row & 255);

    float gval = 0.f;
    if (lane < 27) {
        int l = lane / 3, c = lane - l * 3;
        int node = idx[n * L_SP + l];
        gval = x[(long long)b * (5023 * 3) + node * 3 + c];
    }
    float acc = bs[lane];
#pragma unroll
    for (int k = 0; k < 27; k++) {
        float a = __shfl_sync(0xffffffffu, gval, k);
        acc += a * Ws[k * 32 + lane];
    }
    acc = (acc > 0.f) ? acc : expm1f(acc);
    h[row * 32 + lane] = acc;
}

// ---------------------------------------------------------------------------
// Vectorized gather (float4): out[((n*B+b)*L+l)*C+c] = in[(idx[n,l]*B+b)*C+c]
// ---------------------------------------------------------------------------
__global__ __launch_bounds__(256) void gather4_kernel(
    const float4* __restrict__ in, const int* __restrict__ idx,
    float4* __restrict__ out, int C4, long long total4)
{
    long long i = (long long)blockIdx.x * blockDim.x + threadIdx.x;
    if (i >= total4) return;
    int c4 = (int)(i % C4);
    long long t = i / C4;
    int l = (int)(t % L_SP); t /= L_SP;
    int b = (int)(t % BATCH);
    int n = (int)(t / BATCH);
    long long src = ((long long)idx[n * L_SP + l] * BATCH + b) * C4 + c4;
    out[i] = in[src];
}

// ---------------------------------------------------------------------------
// Final FC (fp32): out[b,l] = sum y3[n*65536+b*256+c] * Wfc[(n*256+c)*128+l]
// ---------------------------------------------------------------------------
__global__ __launch_bounds__(128) void fc_kernel(
    const float* __restrict__ h, const float* __restrict__ W,
    const float* __restrict__ bias, float* __restrict__ out)
{
    __shared__ float s[5120];
    const int b = blockIdx.x;
    for (int k = threadIdx.x; k < 5120; k += 128) {
        int n = k >> 8, c = k & 255;
        s[k] = h[n * 65536 + b * 256 + c];
    }
    __syncthreads();
    float acc = bias[threadIdx.x];
#pragma unroll 8
    for (int k = 0; k < 5120; k++)
        acc += s[k] * W[k * 128 + threadIdx.x];
    out[b * 128 + threadIdx.x] = acc;
}

// ---------------------------------------------------------------------------
// Launch helpers
// ---------------------------------------------------------------------------
static inline void gemm_big(int M, int N, int K, const float* A, const float* B,
                            float* C, const float* bias, int act)
{
    dim3 grid(N / 128, (M + 127) / 128);
    if (K % 4 == 0)
        sgemm_tc<128, 128, 16, 64, 32, true><<<grid, 256>>>(M, N, K, A, B, C, bias, act);
    else
        sgemm_tc<128, 128, 16, 64, 32, false><<<grid, 256>>>(M, N, K, A, B, C, bias, act);
}
static inline void gemm_n64(int M, int N, int K, const float* A, const float* B,
                            float* C, const float* bias, int act)
{
    dim3 grid(N / 64, (M + 127) / 128);
    if (K % 4 == 0)
        sgemm_tc<128, 64, 16, 32, 32, true><<<grid, 256>>>(M, N, K, A, B, C, bias, act);
    else
        sgemm_tc<128, 64, 16, 32, 32, false><<<grid, 256>>>(M, N, K, A, B, C, bias, act);
}
static inline void gemm_m32(int M, int N, int K, const float* A, const float* B,
                            float* C, const float* bias, int act)
{
    dim3 grid(N / 128, (M + 31) / 32);
    if (K % 4 == 0)
        sgemm_tc<32, 128, 16, 16, 32, true><<<grid, 256>>>(M, N, K, A, B, C, bias, act);
    else
        sgemm_tc<32, 128, 16, 16, 32, false><<<grid, 256>>>(M, N, K, A, B, C, bias, act);
}
static inline void launch_gather(const float* in, const int* idx, float* out, int N, int C)
{
    long long total4 = (long long)N * BATCH * L_SP * (C / 4);
    int blocks = (int)((total4 + 255) / 256);
    gather4_kernel<<<blocks, 256>>>((const float4*)in, idx, (float4*)out, C / 4, total4);
}

// ---------------------------------------------------------------------------
// kernel_launch — inputs bound BY ELEMENT COUNT (robust to metadata ordering).
// All sizes unique except b2 & bfc (both 128); b2 precedes bfc.
// ---------------------------------------------------------------------------
extern "C" void kernel_launch(void* const* d_in, const int* in_sizes, int n_in,
                              void* d_out, int out_size)
{
    const void* x = 0; const void* idx0 = 0; const void* idx1 = 0;
    const void* idx2 = 0; const void* idx3 = 0;
    const void* D0 = 0; const void* D1 = 0; const void* D2 = 0; const void* D3 = 0;
    const void* W0 = 0; const void* b0 = 0; const void* W1 = 0; const void* b1 = 0;
    const void* W2 = 0; const void* b2 = 0; const void* W3 = 0; const void* b3 = 0;
    const void* Wfc = 0; const void* bfc = 0;

    for (int i = 0; i < n_in; i++) {
        const void* p = d_in[i];
        switch (in_sizes[i]) {
            case 3857664: x    = p; break;   // 256*5023*3
            case 45207:   idx0 = p; break;   // 5023*9
            case 11304:   idx1 = p; break;   // 1256*9
            case 2826:    idx2 = p; break;   // 314*9
            case 711:     idx3 = p; break;   // 79*9
            case 6308888: D0   = p; break;   // 1256*5023
            case 394384:  D1   = p; break;   // 314*1256
            case 24806:   D2   = p; break;   // 79*314
            case 1580:    D3   = p; break;   // 20*79
            case 864:     W0   = p; break;   // 27*32
            case 32:      b0   = p; break;
            case 18432:   W1   = p; break;   // 288*64
            case 64:      b1   = p; break;
            case 73728:   W2   = p; break;   // 576*128
            case 294912:  W3   = p; break;   // 1152*256
            case 256:     b3   = p; break;
            case 655360:  Wfc  = p; break;   // 5120*128
            case 128:     if (!b2) b2 = p; else bfc = p; break;
            default: break;
        }
    }

    float* out = (float*)d_out;
    float* gb; cudaGetSymbolAddress((void**)&gb, g_buf);
    float* ab; cudaGetSymbolAddress((void**)&ab, a_buf);
    float* yb; cudaGetSymbolAddress((void**)&yb, y_buf);

    // ---- Block 0: fused spiral conv, h0 layout (n=5023, b=256, c=32)
    conv0_kernel<<<(5023 * 256) / 8, 256>>>((const float*)x, (const int*)idx0,
                                            (const float*)W0, (const float*)b0, ab);
    // y0 = D0 @ h0 : (1256 x 5023) @ (5023 x 8192)
    gemm_big(1256, 256 * 32, 5023, (const float*)D0, ab, yb, nullptr, 0);

    // ---- Block 1
    launch_gather(yb, (const int*)idx1, gb, 1256, 32);
    gemm_n64(1256 * 256, 64, 288, gb, (const float*)W1, ab, (const float*)b1, 1);
    gemm_big(314, 256 * 64, 1256, (const float*)D1, ab, yb, nullptr, 0);

    // ---- Block 2
    launch_gather(yb, (const int*)idx2, gb, 314, 64);
    gemm_big(314 * 256, 128, 576, gb, (const float*)W2, ab, (const float*)b2, 1);
    gemm_m32(79, 256 * 128, 314, (const float*)D2, ab, yb, nullptr, 0);

    // ---- Block 3
    launch_gather(yb, (const int*)idx3, gb, 79, 128);
    gemm_big(79 * 256, 256, 1152, gb, (const float*)W3, ab, (const float*)b3, 1);
    gemm_m32(20, 256 * 256, 79, (const float*)D3, ab, yb, nullptr, 0);

    // ---- Final FC: (256 x 5120) @ (5120 x 128), fp32
    fc_kernel<<<256, 128>>>(yb, (const float*)Wfc, (const float*)bfc, out);
}

// round 8
// speedup vs baseline: 3.6782x; 1.1709x over previous
#include <cuda_runtime.h>
#include <cuda_bf16.h>
#include <cstdint>

#define L_SP 9
#define BATCH 256
// Ns = 5023, 1256, 314, 79, 20 ; Cs = 3, 32, 64, 128, 256 ; latent = 128

// ---------------------------------------------------------------------------
// Scratch (device globals; no allocation allowed)
// ---------------------------------------------------------------------------
__device__ float g_buf[92602368];   // gathered spiral rows (max 321536*288)
__device__ float a_buf[41156608];   // conv outputs h_i (5024*8192 for padded h0)
__device__ float y_buf[10289152];   // pooled outputs y_i   (max 1256*256*32)
__device__ float w_buf[7120992];    // tf32-rounded, K-padded D0..D3, W1..W3

// w_buf offsets (floats)
#define OFF_D0P 0          // 1256 x 5024
#define OFF_D1P 6310144    // 314 x 1264
#define OFF_D2P 6707040    // 79 x 320
#define OFF_D3P 6732320    // 20 x 80
#define OFF_W1P 6733920    // 288 x 64
#define OFF_W2P 6752352    // 576 x 128
#define OFF_W3P 6826080    // 1152 x 256

__device__ __forceinline__ float f2tf32(float f) {
    uint32_t r;
    asm("cvt.rna.tf32.f32 %0, %1;" : "=r"(r) : "f"(f));
    return __uint_as_float(r);
}
__device__ __forceinline__ void cpa16(uint32_t dst, const void* src, int sz) {
    asm volatile("cp.async.cg.shared.global [%0], [%1], 16, %2;"
                 :: "r"(dst), "l"(src), "r"(sz));
}
#define CP_COMMIT() asm volatile("cp.async.commit_group;" ::: "memory")
#define CP_WAIT0()  asm volatile("cp.async.wait_group 0;" ::: "memory")

// ---------------------------------------------------------------------------
// tf32 tensor-core GEMM with cp.async double buffering.
// C = round_tf32(act(A(MxK) * B(KxN) + bias))
// Preconditions: K % 16 == 0, N % BN == 0, A/B rows 16B-aligned (K%4==0,N%4==0),
// operands already tf32-rounded. M arbitrary.
// 256 threads = 8 warps; (BM/WM)*(BN/WN) == 8.
// ---------------------------------------------------------------------------
template <int BM, int BN, int WM, int WN>
__global__ __launch_bounds__(256) void gemm_tca(
    int M, int N, int K,
    const float* __restrict__ A, const float* __restrict__ B,
    float* __restrict__ C, const float* __restrict__ bias, int act)
{
    constexpr int BK = 16;
    constexpr int SA = BK + 4;       // A smem row stride (words): m-major [BM][SA]
    constexpr int SB = BN + 8;       // B smem row stride (words): k-major [BK][SB]
    constexpr int NWN = BN / WN;
    constexpr int NWM = BM / WM;
    static_assert(NWM * NWN == 8, "8 warps");
    constexpr int MT = WM / 16;
    constexpr int NT = WN / 8;

    __shared__ float As[2][BM][SA];
    __shared__ float Bs[2][BK][SB];

    const int tid = threadIdx.x;
    const int warp = tid >> 5;
    const int lane = tid & 31;
    const int g = lane >> 2;
    const int tig = lane & 3;
    const int wn0 = (warp % NWN) * WN;
    const int wm0 = (warp / NWN) * WM;
    const int row0 = blockIdx.y * BM;
    const int col0 = blockIdx.x * BN;

    const uint32_t sA = (uint32_t)__cvta_generic_to_shared(&As[0][0][0]);
    const uint32_t sB = (uint32_t)__cvta_generic_to_shared(&Bs[0][0][0]);

    constexpr int AF4 = BM * 4;          // float4 slots in A tile
    constexpr int A_IT = (AF4 + 255) / 256;
    constexpr int BF4 = 4 * BN;          // float4 slots in B tile (16 rows * BN/4)
    constexpr int B_IT = (BF4 + 255) / 256;
    constexpr int NQ = BN / 4;

    float acc[MT][NT][4];
#pragma unroll
    for (int i = 0; i < MT; i++)
#pragma unroll
        for (int j = 0; j < NT; j++)
#pragma unroll
            for (int v = 0; v < 4; v++) acc[i][j][v] = 0.f;

    const int ktiles = K / BK;

    auto issue = [&](int t, int bf) {
#pragma unroll
        for (int i = 0; i < A_IT; i++) {
            int lin = tid + i * 256;
            if ((AF4 % 256 == 0) || (lin < AF4)) {
                int m = lin >> 2;
                int kq = lin & 3;
                int gm = row0 + m;
                int sz = (gm < M) ? 16 : 0;
                int gmc = (gm < M) ? gm : (M - 1);
                const float* src = A + (long long)gmc * K + t * BK + kq * 4;
                uint32_t dst = sA + (((bf * BM + m) * SA) + kq * 4) * 4u;
                cpa16(dst, src, sz);
            }
        }
#pragma unroll
        for (int i = 0; i < B_IT; i++) {
            int lin = tid + i * 256;
            if ((BF4 % 256 == 0) || (lin < BF4)) {
                int k = lin / NQ;
                int n4 = lin % NQ;
                const float* src = B + (long long)(t * BK + k) * N + col0 + n4 * 4;
                uint32_t dst = sB + (((bf * BK + k) * SB) + n4 * 4) * 4u;
                cpa16(dst, src, 16);
            }
        }
    };

    issue(0, 0);
    CP_COMMIT();

    const float* Af = &As[0][0][0];
    const float* Bf = &Bs[0][0][0];

    int bf = 0;
    for (int t = 0; t < ktiles; t++) {
        CP_WAIT0();
        __syncthreads();
        if (t + 1 < ktiles) {
            issue(t + 1, bf ^ 1);
            CP_COMMIT();
        }
        const int aBase = bf * BM * SA + (wm0 + g) * SA;
        const int bBase = bf * BK * SB + wn0 + g;
#pragma unroll
        for (int kt = 0; kt < 2; kt++) {
            uint32_t af[MT][4], bfr[NT][2];
#pragma unroll
            for (int mt = 0; mt < MT; mt++) {
                int a0 = aBase + mt * 16 * SA + kt * 8 + tig;
                af[mt][0] = __float_as_uint(Af[a0]);
                af[mt][1] = __float_as_uint(Af[a0 + 8 * SA]);
                af[mt][2] = __float_as_uint(Af[a0 + 4]);
                af[mt][3] = __float_as_uint(Af[a0 + 8 * SA + 4]);
            }
#pragma unroll
            for (int nt = 0; nt < NT; nt++) {
                int b0 = bBase + (kt * 8 + tig) * SB + nt * 8;
                bfr[nt][0] = __float_as_uint(Bf[b0]);
                bfr[nt][1] = __float_as_uint(Bf[b0 + 4 * SB]);
            }
#pragma unroll
            for (int mt = 0; mt < MT; mt++)
#pragma unroll
                for (int nt = 0; nt < NT; nt++) {
                    asm volatile(
                        "mma.sync.aligned.m16n8k8.row.col.f32.tf32.tf32.f32 "
                        "{%0,%1,%2,%3}, {%4,%5,%6,%7}, {%8,%9}, {%0,%1,%2,%3};"
                        : "+f"(acc[mt][nt][0]), "+f"(acc[mt][nt][1]),
                          "+f"(acc[mt][nt][2]), "+f"(acc[mt][nt][3])
                        : "r"(af[mt][0]), "r"(af[mt][1]), "r"(af[mt][2]), "r"(af[mt][3]),
                          "r"(bfr[nt][0]), "r"(bfr[nt][1]));
                }
        }
        bf ^= 1;
    }

    // Epilogue: c0,c1 -> (row g, cols 2*tig..); c2,c3 -> row g+8. Round to tf32.
#pragma unroll
    for (int mt = 0; mt < MT; mt++) {
#pragma unroll
        for (int nt = 0; nt < NT; nt++) {
            int gn = col0 + wn0 + nt * 8 + 2 * tig;
            float bv0 = bias ? bias[gn] : 0.f;
            float bv1 = bias ? bias[gn + 1] : 0.f;
            int r0 = row0 + wm0 + mt * 16 + g;
            int r1 = r0 + 8;
            if (r0 < M) {
                float v0 = acc[mt][nt][0] + bv0;
                float v1 = acc[mt][nt][1] + bv1;
                if (act) {
                    v0 = (v0 > 0.f) ? v0 : expm1f(v0);
                    v1 = (v1 > 0.f) ? v1 : expm1f(v1);
                }
                *(float2*)&C[(long long)r0 * N + gn] =
                    make_float2(f2tf32(v0), f2tf32(v1));
            }
            if (r1 < M) {
                float v0 = acc[mt][nt][2] + bv0;
                float v1 = acc[mt][nt][3] + bv1;
                if (act) {
                    v0 = (v0 > 0.f) ? v0 : expm1f(v0);
                    v1 = (v1 > 0.f) ? v1 : expm1f(v1);
                }
                *(float2*)&C[(long long)r1 * N + gn] =
                    make_float2(f2tf32(v0), f2tf32(v1));
            }
        }
    }
}

// ---------------------------------------------------------------------------
// Pre-pass: round src to tf32 and zero-pad rows from kin to kout columns.
// dst[r*kout + k] = k < kin ? tf32(src[r*kin + k]) : 0
// ---------------------------------------------------------------------------
__global__ __launch_bounds__(256) void round_pad_kernel(
    const float* __restrict__ src, float* __restrict__ dst,
    int kin, int kout, long long total)
{
    long long i = (long long)blockIdx.x * blockDim.x + threadIdx.x;
    if (i >= total) return;
    int k = (int)(i % kout);
    long long r = i / kout;
    dst[i] = (k < kin) ? f2tf32(src[r * kin + k]) : 0.f;
}

// ---------------------------------------------------------------------------
// Stage-0 fused spiral conv (writes tf32-rounded h0, zero row at n=5023).
// x: (B,5023,3) ; idx: (5023,9) ; W: (27,32) ; h out: (5024,256,32)
// ---------------------------------------------------------------------------
__global__ __launch_bounds__(256) void conv0_kernel(
    const float* __restrict__ x, const int* __restrict__ idx,
    const float* __restrict__ W, const float* __restrict__ bias,
    float* __restrict__ h)
{
    __shared__ float Ws[27 * 32];
    __shared__ float bs[32];
    const int tid = threadIdx.x;
    for (int i = tid; i < 27 * 32; i += 256) Ws[i] = W[i];
    if (tid < 32) bs[tid] = bias[tid];
    __syncthreads();

    const int warp = tid >> 5, lane = tid & 31;
    const long long row = (long long)blockIdx.x * 8 + warp;  // n*256 + b
    const int n = (int)(row >> 8);
    const int b = (int)(row & 255);

    if (n >= 5023) {           // zero pad row (K padded to 5024 for D0)
        h[row * 32 + lane] = 0.f;
        return;
    }

    float gval = 0.f;
    if (lane < 27) {
        int l = lane / 3, c = lane - l * 3;
        int node = idx[n * L_SP + l];
        gval = x[(long long)b * (5023 * 3) + node * 3 + c];
    }
    float acc = bs[lane];
#pragma unroll
    for (int k = 0; k < 27; k++) {
        float a = __shfl_sync(0xffffffffu, gval, k);
        acc += a * Ws[k * 32 + lane];
    }
    acc = (acc > 0.f) ? acc : expm1f(acc);
    h[row * 32 + lane] = f2tf32(acc);
}

// ---------------------------------------------------------------------------
// Vectorized gather (float4): out[((n*B+b)*L+l)*C+c] = in[(idx[n,l]*B+b)*C+c]
// ---------------------------------------------------------------------------
__global__ __launch_bounds__(256) void gather4_kernel(
    const float4* __restrict__ in, const int* __restrict__ idx,
    float4* __restrict__ out, int C4, long long total4)
{
    long long i = (long long)blockIdx.x * blockDim.x + threadIdx.x;
    if (i >= total4) return;
    int c4 = (int)(i % C4);
    long long t = i / C4;
    int l = (int)(t % L_SP); t /= L_SP;
    int b = (int)(t % BATCH);
    int n = (int)(t / BATCH);
    long long src = ((long long)idx[n * L_SP + l] * BATCH + b) * C4 + c4;
    out[i] = in[src];
}

// ---------------------------------------------------------------------------
// Final FC (fp32): out[b,l] = sum y3[n*65536+b*256+c] * Wfc[(n*256+c)*128+l]
// ---------------------------------------------------------------------------
__global__ __launch_bounds__(128) void fc_kernel(
    const float* __restrict__ h, const float* __restrict__ W,
    const float* __restrict__ bias, float* __restrict__ out)
{
    __shared__ float s[5120];
    const int b = blockIdx.x;
    for (int k = threadIdx.x; k < 5120; k += 128) {
        int n = k >> 8, c = k & 255;
        s[k] = h[n * 65536 + b * 256 + c];
    }
    __syncthreads();
    float acc = bias[threadIdx.x];
#pragma unroll 8
    for (int k = 0; k < 5120; k++)
        acc += s[k] * W[k * 128 + threadIdx.x];
    out[b * 128 + threadIdx.x] = acc;
}

// ---------------------------------------------------------------------------
// Launch helpers
// ---------------------------------------------------------------------------
static inline void gemm_big(int M, int N, int K, const float* A, const float* B,
                            float* C, const float* bias, int act)
{
    dim3 grid(N / 128, (M + 127) / 128);
    gemm_tca<128, 128, 64, 32><<<grid, 256>>>(M, N, K, A, B, C, bias, act);
}
static inline void gemm_n64(int M, int N, int K, const float* A, const float* B,
                            float* C, const float* bias, int act)
{
    dim3 grid(N / 64, (M + 127) / 128);
    gemm_tca<128, 64, 32, 32><<<grid, 256>>>(M, N, K, A, B, C, bias, act);
}
static inline void gemm_m32(int M, int N, int K, const float* A, const float* B,
                            float* C, const float* bias, int act)
{
    dim3 grid(N / 128, (M + 31) / 32);
    gemm_tca<32, 128, 16, 32><<<grid, 256>>>(M, N, K, A, B, C, bias, act);
}
static inline void launch_gather(const float* in, const int* idx, float* out, int N, int C)
{
    long long total4 = (long long)N * BATCH * L_SP * (C / 4);
    int blocks = (int)((total4 + 255) / 256);
    gather4_kernel<<<blocks, 256>>>((const float4*)in, idx, (float4*)out, C / 4, total4);
}
static inline void launch_round_pad(const float* src, float* dst, int rows, int kin, int kout)
{
    long long total = (long long)rows * kout;
    int blocks = (int)((total + 255) / 256);
    round_pad_kernel<<<blocks, 256>>>(src, dst, kin, kout, total);
}

// ---------------------------------------------------------------------------
// kernel_launch — inputs bound BY ELEMENT COUNT (robust to metadata ordering).
// All sizes unique except b2 & bfc (both 128); b2 precedes bfc.
// ---------------------------------------------------------------------------
extern "C" void kernel_launch(void* const* d_in, const int* in_sizes, int n_in,
                              void* d_out, int out_size)
{
    const void* x = 0; const void* idx0 = 0; const void* idx1 = 0;
    const void* idx2 = 0; const void* idx3 = 0;
    const void* D0 = 0; const void* D1 = 0; const void* D2 = 0; const void* D3 = 0;
    const void* W0 = 0; const void* b0 = 0; const void* W1 = 0; const void* b1 = 0;
    const void* W2 = 0; const void* b2 = 0; const void* W3 = 0; const void* b3 = 0;
    const void* Wfc = 0; const void* bfc = 0;

    for (int i = 0; i < n_in; i++) {
        const void* p = d_in[i];
        switch (in_sizes[i]) {
            case 3857664: x    = p; break;   // 256*5023*3
            case 45207:   idx0 = p; break;   // 5023*9
            case 11304:   idx1 = p; break;   // 1256*9
            case 2826:    idx2 = p; break;   // 314*9
            case 711:     idx3 = p; break;   // 79*9
            case 6308888: D0   = p; break;   // 1256*5023
            case 394384:  D1   = p; break;   // 314*1256
            case 24806:   D2   = p; break;   // 79*314
            case 1580:    D3   = p; break;   // 20*79
            case 864:     W0   = p; break;   // 27*32
            case 32:      b0   = p; break;
            case 18432:   W1   = p; break;   // 288*64
            case 64:      b1   = p; break;
            case 73728:   W2   = p; break;   // 576*128
            case 294912:  W3   = p; break;   // 1152*256
            case 256:     b3   = p; break;
            case 655360:  Wfc  = p; break;   // 5120*128
            case 128:     if (!b2) b2 = p; else bfc = p; break;
            default: break;
        }
    }

    float* out = (float*)d_out;
    float* gb; cudaGetSymbolAddress((void**)&gb, g_buf);
    float* ab; cudaGetSymbolAddress((void**)&ab, a_buf);
    float* yb; cudaGetSymbolAddress((void**)&yb, y_buf);
    float* wb; cudaGetSymbolAddress((void**)&wb, w_buf);

    float* d0p = wb + OFF_D0P;
    float* d1p = wb + OFF_D1P;
    float* d2p = wb + OFF_D2P;
    float* d3p = wb + OFF_D3P;
    float* w1p = wb + OFF_W1P;
    float* w2p = wb + OFF_W2P;
    float* w3p = wb + OFF_W3P;

    // ---- Pre-pass: tf32-round (and K-pad) all static GEMM operands
    launch_round_pad((const float*)D0, d0p, 1256, 5023, 5024);
    launch_round_pad((const float*)D1, d1p, 314, 1256, 1264);
    launch_round_pad((const float*)D2, d2p, 79, 314, 320);
    launch_round_pad((const float*)D3, d3p, 20, 79, 80);
    launch_round_pad((const float*)W1, w1p, 1, 18432, 18432);
    launch_round_pad((const float*)W2, w2p, 1, 73728, 73728);
    launch_round_pad((const float*)W3, w3p, 1, 294912, 294912);

    // ---- Block 0: fused spiral conv, h0 (5024,256,32) tf32-rounded
    conv0_kernel<<<(5024 * 256) / 8, 256>>>((const float*)x, (const int*)idx0,
                                            (const float*)W0, (const float*)b0, ab);
    // y0 = D0p @ h0 : (1256 x 5024) @ (5024 x 8192)
    gemm_big(1256, 256 * 32, 5024, d0p, ab, yb, nullptr, 0);

    // ---- Block 1
    launch_gather(yb, (const int*)idx1, gb, 1256, 32);
    gemm_n64(1256 * 256, 64, 288, gb, w1p, ab, (const float*)b1, 1);
    gemm_big(314, 256 * 64, 1264, d1p, ab, yb, nullptr, 0);

    // ---- Block 2
    launch_gather(yb, (const int*)idx2, gb, 314, 64);
    gemm_big(314 * 256, 128, 576, gb, w2p, ab, (const float*)b2, 1);
    gemm_m32(79, 256 * 128, 320, d2p, ab, yb, nullptr, 0);

    // ---- Block 3
    launch_gather(yb, (const int*)idx3, gb, 79, 128);
    gemm_big(79 * 256, 256, 1152, gb, w3p, ab, (const float*)b3, 1);
    gemm_m32(20, 256 * 256, 80, d3p, ab, yb, nullptr, 0);

    // ---- Final FC: (256 x 5120) @ (5120 x 128), fp32
    fc_kernel<<<256, 128>>>(yb, (const float*)Wfc, (const float*)bfc, out);
}

// round 10
// speedup vs baseline: 4.4836x; 1.2190x over previous
#include <cuda_runtime.h>
#include <cuda_bf16.h>
#include <cstdint>

#define L_SP 9
#define BATCH 256
// Ns = 5023, 1256, 314, 79, 20 ; Cs = 3, 32, 64, 128, 256 ; latent = 128

// ---------------------------------------------------------------------------
// Scratch (device globals; no allocation allowed)
// ---------------------------------------------------------------------------
__device__ float a_buf[41156608];   // conv outputs h_i (5024*8192 for padded h0)
__device__ float y_buf[10289152];   // pooled outputs y_i   (max 1256*256*32)
__device__ float w_buf[7120992];    // tf32-rounded, K-padded D0..D3, W1..W3

// w_buf offsets (floats)
#define OFF_D0P 0          // 1256 x 5024
#define OFF_D1P 6310144    // 314 x 1264
#define OFF_D2P 6707040    // 79 x 320
#define OFF_D3P 6732320    // 20 x 80
#define OFF_W1P 6733920    // 288 x 64
#define OFF_W2P 6752352    // 576 x 128
#define OFF_W3P 6826080    // 1152 x 256

__device__ __forceinline__ float f2tf32(float f) {
    uint32_t r;
    asm("cvt.rna.tf32.f32 %0, %1;" : "=r"(r) : "f"(f));
    return __uint_as_float(r);
}
__device__ __forceinline__ void cpa16(uint32_t dst, const void* src, int sz) {
    asm volatile("cp.async.cg.shared.global [%0], [%1], 16, %2;"
                 :: "r"(dst), "l"(src), "r"(sz));
}
#define CP_COMMIT() asm volatile("cp.async.commit_group;" ::: "memory")
#define CP_WAIT1()  asm volatile("cp.async.wait_group 1;" ::: "memory")

#define SA 20   // A smem row stride (BK=16 + 4 pad)
#define BKT 16

// ===========================================================================
// MMA mainloop body shared by both GEMMs.
// ===========================================================================
#define MMA_TILE_COMPUTE(Af, Bf, s, BM, SB)                                     \
    {                                                                           \
        const int aBase = (s) * (BM) * SA + (wm0 + g) * SA;                     \
        const int bBase = (s) * BKT * (SB) + wn0 + g;                           \
        _Pragma("unroll")                                                       \
        for (int kt = 0; kt < 2; kt++) {                                        \
            uint32_t af[MT][4], bfr[NT][2];                                     \
            _Pragma("unroll")                                                   \
            for (int mt = 0; mt < MT; mt++) {                                   \
                int a0 = aBase + mt * 16 * SA + kt * 8 + tig;                   \
                af[mt][0] = __float_as_uint(Af[a0]);                            \
                af[mt][1] = __float_as_uint(Af[a0 + 8 * SA]);                   \
                af[mt][2] = __float_as_uint(Af[a0 + 4]);                        \
                af[mt][3] = __float_as_uint(Af[a0 + 8 * SA + 4]);               \
            }                                                                   \
            _Pragma("unroll")                                                   \
            for (int nt = 0; nt < NT; nt++) {                                   \
                int b0i = bBase + (kt * 8 + tig) * (SB) + nt * 8;               \
                bfr[nt][0] = __float_as_uint(Bf[b0i]);                          \
                bfr[nt][1] = __float_as_uint(Bf[b0i + 4 * (SB)]);               \
            }                                                                   \
            _Pragma("unroll")                                                   \
            for (int mt = 0; mt < MT; mt++)                                     \
                _Pragma("unroll")                                               \
                for (int nt = 0; nt < NT; nt++) {                               \
                    asm volatile(                                               \
                        "mma.sync.aligned.m16n8k8.row.col.f32.tf32.tf32.f32 "   \
                        "{%0,%1,%2,%3}, {%4,%5,%6,%7}, {%8,%9}, {%0,%1,%2,%3};" \
                        : "+f"(acc[mt][nt][0]), "+f"(acc[mt][nt][1]),           \
                          "+f"(acc[mt][nt][2]), "+f"(acc[mt][nt][3])            \
                        : "r"(af[mt][0]), "r"(af[mt][1]),                       \
                          "r"(af[mt][2]), "r"(af[mt][3]),                       \
                          "r"(bfr[nt][0]), "r"(bfr[nt][1]));                    \
                }                                                               \
        }                                                                       \
    }

// ---------------------------------------------------------------------------
// tf32 GEMM, 3-stage cp.async, dynamic smem.
// C = round_tf32(act(A(MxK) * B(KxN) + bias))
// K % 16 == 0, N % BN == 0, operands tf32-rounded, rows 16B-aligned. M free.
// ---------------------------------------------------------------------------
template <int BM, int BN, int WM, int WN>
__global__ __launch_bounds__(256) void gemm_tca(
    int M, int N, int K,
    const float* __restrict__ A, const float* __restrict__ B,
    float* __restrict__ C, const float* __restrict__ bias, int act)
{
    constexpr int SB = BN + 8;
    constexpr int NWN = BN / WN;
    constexpr int NWM = BM / WM;
    static_assert(NWM * NWN == 8, "8 warps");
    constexpr int MT = WM / 16;
    constexpr int NT = WN / 8;

    extern __shared__ float smem[];
    float* Af = smem;                      // 3 * BM * SA
    float* Bf = smem + 3 * BM * SA;        // 3 * BKT * SB

    const int tid = threadIdx.x;
    const int warp = tid >> 5;
    const int lane = tid & 31;
    const int g = lane >> 2;
    const int tig = lane & 3;
    const int wn0 = (warp % NWN) * WN;
    const int wm0 = (warp / NWN) * WM;
    const int row0 = blockIdx.y * BM;
    const int col0 = blockIdx.x * BN;

    const uint32_t sA = (uint32_t)__cvta_generic_to_shared(Af);
    const uint32_t sB = (uint32_t)__cvta_generic_to_shared(Bf);

    constexpr int AF4 = BM * 4;
    constexpr int A_IT = (AF4 + 255) / 256;
    constexpr int BF4 = 4 * BN;
    constexpr int B_IT = (BF4 + 255) / 256;
    constexpr int NQ = BN / 4;

    float acc[MT][NT][4];
#pragma unroll
    for (int i = 0; i < MT; i++)
#pragma unroll
        for (int j = 0; j < NT; j++)
#pragma unroll
            for (int v = 0; v < 4; v++) acc[i][j][v] = 0.f;

    const int ktiles = K / BKT;

    auto issue = [&](int t, int s) {
#pragma unroll
        for (int i = 0; i < A_IT; i++) {
            int lin = tid + i * 256;
            if ((AF4 % 256 == 0) || (lin < AF4)) {
                int m = lin >> 2;
                int kq = lin & 3;
                int gm = row0 + m;
                int sz = (gm < M) ? 16 : 0;
                int gmc = (gm < M) ? gm : (M - 1);
                const float* src = A + (long long)gmc * K + t * BKT + kq * 4;
                uint32_t dst = sA + (((s * BM + m) * SA) + kq * 4) * 4u;
                cpa16(dst, src, sz);
            }
        }
#pragma unroll
        for (int i = 0; i < B_IT; i++) {
            int lin = tid + i * 256;
            if ((BF4 % 256 == 0) || (lin < BF4)) {
                int k = lin / NQ;
                int n4 = lin % NQ;
                const float* src = B + (long long)(t * BKT + k) * N + col0 + n4 * 4;
                uint32_t dst = sB + (((s * BKT + k) * SB) + n4 * 4) * 4u;
                cpa16(dst, src, 16);
            }
        }
    };

    issue(0, 0); CP_COMMIT();
    issue(1, 1); CP_COMMIT();

    int s = 0;
    for (int t = 0; t < ktiles; t++) {
        CP_WAIT1();
        __syncthreads();
        MMA_TILE_COMPUTE(Af, Bf, s, BM, SB);
        if (t + 2 < ktiles) {
            int s2 = s + 2; if (s2 >= 3) s2 -= 3;
            issue(t + 2, s2);
        }
        CP_COMMIT();   // ALWAYS commit (empty group at tail) so wait_group 1
                       // provably drains group t on every iteration incl. last
        if (++s == 3) s = 0;
    }

#pragma unroll
    for (int mt = 0; mt < MT; mt++) {
#pragma unroll
        for (int nt = 0; nt < NT; nt++) {
            int gn = col0 + wn0 + nt * 8 + 2 * tig;
            float bv0 = bias ? bias[gn] : 0.f;
            float bv1 = bias ? bias[gn + 1] : 0.f;
            int r0 = row0 + wm0 + mt * 16 + g;
            int r1 = r0 + 8;
            if (r0 < M) {
                float v0 = acc[mt][nt][0] + bv0;
                float v1 = acc[mt][nt][1] + bv1;
                if (act) { v0 = (v0 > 0.f) ? v0 : expm1f(v0);
                           v1 = (v1 > 0.f) ? v1 : expm1f(v1); }
                *(float2*)&C[(long long)r0 * N + gn] =
                    make_float2(f2tf32(v0), f2tf32(v1));
            }
            if (r1 < M) {
                float v0 = acc[mt][nt][2] + bv0;
                float v1 = acc[mt][nt][3] + bv1;
                if (act) { v0 = (v0 > 0.f) ? v0 : expm1f(v0);
                           v1 = (v1 > 0.f) ? v1 : expm1f(v1); }
                *(float2*)&C[(long long)r1 * N + gn] =
                    make_float2(f2tf32(v0), f2tf32(v1));
            }
        }
    }
}

// ---------------------------------------------------------------------------
// Fused gather + conv GEMM. A is the IMPLICIT spiral-gathered matrix:
//   A[row=(n*256+b)][k=l*C+c] = Y[(idx[n*9+l]*256 + b)*C + c]
// BM=128 -> each block has ONE node n. h = round_tf32(elu(A@W + bias)).
// K = 9*C (mult of 16). M % 128 == 0.
// ---------------------------------------------------------------------------
template <int C, int BN, int WM, int WN>
__global__ __launch_bounds__(256) void gemm_conv(
    int M, int N,
    const float* __restrict__ Y, const int* __restrict__ idx,
    const float* __restrict__ W, float* __restrict__ H,
    const float* __restrict__ bias)
{
    constexpr int BM = 128;
    constexpr int K = 9 * C;
    constexpr int SB = BN + 8;
    constexpr int NWN = BN / WN;
    constexpr int NWM = BM / WM;
    static_assert(NWM * NWN == 8, "8 warps");
    constexpr int MT = WM / 16;
    constexpr int NT = WN / 8;

    extern __shared__ float smem[];
    float* Af = smem;
    float* Bf = smem + 3 * BM * SA;
    __shared__ int idx_s[L_SP];

    const int tid = threadIdx.x;
    const int warp = tid >> 5;
    const int lane = tid & 31;
    const int g = lane >> 2;
    const int tig = lane & 3;
    const int wn0 = (warp % NWN) * WN;
    const int wm0 = (warp / NWN) * WM;
    const int row0 = blockIdx.y * BM;
    const int col0 = blockIdx.x * BN;
    const int n = row0 >> 8;
    const int b0 = row0 & 255;

    if (tid < L_SP) idx_s[tid] = idx[n * L_SP + tid];
    __syncthreads();

    const uint32_t sA = (uint32_t)__cvta_generic_to_shared(Af);
    const uint32_t sB = (uint32_t)__cvta_generic_to_shared(Bf);

    constexpr int BF4 = 4 * BN;
    constexpr int B_IT = (BF4 + 255) / 256;
    constexpr int NQ = BN / 4;

    float acc[MT][NT][4];
#pragma unroll
    for (int i = 0; i < MT; i++)
#pragma unroll
        for (int j = 0; j < NT; j++)
#pragma unroll
            for (int v = 0; v < 4; v++) acc[i][j][v] = 0.f;

    constexpr int ktiles = K / BKT;

    auto issue = [&](int t, int s) {
#pragma unroll
        for (int i = 0; i < 2; i++) {        // AF4 = 512
            int lin = tid + i * 256;
            int m = lin >> 2;
            int kq = lin & 3;
            int col = t * BKT + kq * 4;
            int l = col / C;                  // compile-time C -> shifts
            int c = col % C;
            int node = idx_s[l];
            const float* src = Y + ((long long)(node * 256 + b0 + m)) * C + c;
            uint32_t dst = sA + (((s * BM + m) * SA) + kq * 4) * 4u;
            cpa16(dst, src, 16);
        }
#pragma unroll
        for (int i = 0; i < B_IT; i++) {
            int lin = tid + i * 256;
            if ((BF4 % 256 == 0) || (lin < BF4)) {
                int k = lin / NQ;
                int n4 = lin % NQ;
                const float* src = W + (long long)(t * BKT + k) * N + col0 + n4 * 4;
                uint32_t dst = sB + (((s * BKT + k) * SB) + n4 * 4) * 4u;
                cpa16(dst, src, 16);
            }
        }
    };

    issue(0, 0); CP_COMMIT();
    issue(1, 1); CP_COMMIT();

    int s = 0;
    for (int t = 0; t < ktiles; t++) {
        CP_WAIT1();
        __syncthreads();
        MMA_TILE_COMPUTE(Af, Bf, s, BM, SB);
        if (t + 2 < ktiles) {
            int s2 = s + 2; if (s2 >= 3) s2 -= 3;
            issue(t + 2, s2);
        }
        CP_COMMIT();   // ALWAYS commit (empty group at tail) — see gemm_tca
        if (++s == 3) s = 0;
    }

#pragma unroll
    for (int mt = 0; mt < MT; mt++) {
#pragma unroll
        for (int nt = 0; nt < NT; nt++) {
            int gn = col0 + wn0 + nt * 8 + 2 * tig;
            float bv0 = bias[gn];
            float bv1 = bias[gn + 1];
            int r0 = row0 + wm0 + mt * 16 + g;
            int r1 = r0 + 8;
            {
                float v0 = acc[mt][nt][0] + bv0;
                float v1 = acc[mt][nt][1] + bv1;
                v0 = (v0 > 0.f) ? v0 : expm1f(v0);
                v1 = (v1 > 0.f) ? v1 : expm1f(v1);
                *(float2*)&H[(long long)r0 * N + gn] =
                    make_float2(f2tf32(v0), f2tf32(v1));
            }
            {
                float v0 = acc[mt][nt][2] + bv0;
                float v1 = acc[mt][nt][3] + bv1;
                v0 = (v0 > 0.f) ? v0 : expm1f(v0);
                v1 = (v1 > 0.f) ? v1 : expm1f(v1);
                *(float2*)&H[(long long)r1 * N + gn] =
                    make_float2(f2tf32(v0), f2tf32(v1));
            }
        }
    }
}

// ---------------------------------------------------------------------------
// Pre-pass: round src to tf32 and zero-pad rows from kin to kout columns.
// ---------------------------------------------------------------------------
__global__ __launch_bounds__(256) void round_pad_kernel(
    const float* __restrict__ src, float* __restrict__ dst,
    int kin, int kout, long long total)
{
    long long i = (long long)blockIdx.x * blockDim.x + threadIdx.x;
    if (i >= total) return;
    int k = (int)(i % kout);
    long long r = i / kout;
    dst[i] = (k < kin) ? f2tf32(src[r * kin + k]) : 0.f;
}

// ---------------------------------------------------------------------------
// Stage-0 fused spiral conv (tf32-rounded h0, zero row at n=5023).
// ---------------------------------------------------------------------------
__global__ __launch_bounds__(256) void conv0_kernel(
    const float* __restrict__ x, const int* __restrict__ idx,
    const float* __restrict__ W, const float* __restrict__ bias,
    float* __restrict__ h)
{
    __shared__ float Ws[27 * 32];
    __shared__ float bs[32];
    const int tid = threadIdx.x;
    for (int i = tid; i < 27 * 32; i += 256) Ws[i] = W[i];
    if (tid < 32) bs[tid] = bias[tid];
    __syncthreads();

    const int warp = tid >> 5, lane = tid & 31;
    const long long row = (long long)blockIdx.x * 8 + warp;
    const int n = (int)(row >> 8);
    const int b = (int)(row & 255);

    if (n >= 5023) { h[row * 32 + lane] = 0.f; return; }

    float gval = 0.f;
    if (lane < 27) {
        int l = lane / 3, c = lane - l * 3;
        int node = idx[n * L_SP + l];
        gval = x[(long long)b * (5023 * 3) + node * 3 + c];
    }
    float acc = bs[lane];
#pragma unroll
    for (int k = 0; k < 27; k++) {
        float a = __shfl_sync(0xffffffffu, gval, k);
        acc += a * Ws[k * 32 + lane];
    }
    acc = (acc > 0.f) ? acc : expm1f(acc);
    h[row * 32 + lane] = f2tf32(acc);
}

// ---------------------------------------------------------------------------
// Final FC (fp32)
// ---------------------------------------------------------------------------
__global__ __launch_bounds__(128) void fc_kernel(
    const float* __restrict__ h, const float* __restrict__ W,
    const float* __restrict__ bias, float* __restrict__ out)
{
    __shared__ float s[5120];
    const int b = blockIdx.x;
    for (int k = threadIdx.x; k < 5120; k += 128) {
        int n = k >> 8, c = k & 255;
        s[k] = h[n * 65536 + b * 256 + c];
    }
    __syncthreads();
    float acc = bias[threadIdx.x];
#pragma unroll 8
    for (int k = 0; k < 5120; k++)
        acc += s[k] * W[k * 128 + threadIdx.x];
    out[b * 128 + threadIdx.x] = acc;
}

// ---------------------------------------------------------------------------
// Launch helpers
// ---------------------------------------------------------------------------
static inline int smem_bytes(int BM, int BN) {
    return (3 * BM * SA + 3 * BKT * (BN + 8)) * 4;
}

static inline void gemm_big(int M, int N, int K, const float* A, const float* B,
                            float* C, const float* bias, int act)
{
    int sm = smem_bytes(128, 128);
    cudaFuncSetAttribute(gemm_tca<128, 128, 64, 32>,
                         cudaFuncAttributeMaxDynamicSharedMemorySize, sm);
    dim3 grid(N / 128, (M + 127) / 128);
    gemm_tca<128, 128, 64, 32><<<grid, 256, sm>>>(M, N, K, A, B, C, bias, act);
}
static inline void gemm_m32(int M, int N, int K, const float* A, const float* B,
                            float* C, const float* bias, int act)
{
    int sm = smem_bytes(32, 128);
    cudaFuncSetAttribute(gemm_tca<32, 128, 16, 32>,
                         cudaFuncAttributeMaxDynamicSharedMemorySize, sm);
    dim3 grid(N / 128, (M + 31) / 32);
    gemm_tca<32, 128, 16, 32><<<grid, 256, sm>>>(M, N, K, A, B, C, bias, act);
}
template <int C, int BN, int WM, int WN>
static inline void conv_fused(int M, int N, const float* Y, const int* idx,
                              const float* W, float* H, const float* bias)
{
    int sm = smem_bytes(128, BN);
    cudaFuncSetAttribute(gemm_conv<C, BN, WM, WN>,
                         cudaFuncAttributeMaxDynamicSharedMemorySize, sm);
    dim3 grid(N / BN, M / 128);
    gemm_conv<C, BN, WM, WN><<<grid, 256, sm>>>(M, N, Y, idx, W, H, bias);
}
static inline void launch_round_pad(const float* src, float* dst, int rows, int kin, int kout)
{
    long long total = (long long)rows * kout;
    int blocks = (int)((total + 255) / 256);
    round_pad_kernel<<<blocks, 256>>>(src, dst, kin, kout, total);
}

// ---------------------------------------------------------------------------
// kernel_launch — inputs bound BY ELEMENT COUNT.
// All sizes unique except b2 & bfc (both 128); b2 precedes bfc.
// ---------------------------------------------------------------------------
extern "C" void kernel_launch(void* const* d_in, const int* in_sizes, int n_in,
                              void* d_out, int out_size)
{
    const void* x = 0; const void* idx0 = 0; const void* idx1 = 0;
    const void* idx2 = 0; const void* idx3 = 0;
    const void* D0 = 0; const void* D1 = 0; const void* D2 = 0; const void* D3 = 0;
    const void* W0 = 0; const void* b0 = 0; const void* W1 = 0; const void* b1 = 0;
    const void* W2 = 0; const void* b2 = 0; const void* W3 = 0; const void* b3 = 0;
    const void* Wfc = 0; const void* bfc = 0;

    for (int i = 0; i < n_in; i++) {
        const void* p = d_in[i];
        switch (in_sizes[i]) {
            case 3857664: x    = p; break;   // 256*5023*3
            case 45207:   idx0 = p; break;   // 5023*9
            case 11304:   idx1 = p; break;   // 1256*9
            case 2826:    idx2 = p; break;   // 314*9
            case 711:     idx3 = p; break;   // 79*9
            case 6308888: D0   = p; break;   // 1256*5023
            case 394384:  D1   = p; break;   // 314*1256
            case 24806:   D2   = p; break;   // 79*314
            case 1580:    D3   = p; break;   // 20*79
            case 864:     W0   = p; break;   // 27*32
            case 32:      b0   = p; break;
            case 18432:   W1   = p; break;   // 288*64
            case 64:      b1   = p; break;
            case 73728:   W2   = p; break;   // 576*128
            case 294912:  W3   = p; break;   // 1152*256
            case 256:     b3   = p; break;
            case 655360:  Wfc  = p; break;   // 5120*128
            case 128:     if (!b2) b2 = p; else bfc = p; break;
            default: break;
        }
    }

    float* out = (float*)d_out;
    float* ab; cudaGetSymbolAddress((void**)&ab, a_buf);
    float* yb; cudaGetSymbolAddress((void**)&yb, y_buf);
    float* wb; cudaGetSymbolAddress((void**)&wb, w_buf);

    float* d0p = wb + OFF_D0P;
    float* d1p = wb + OFF_D1P;
    float* d2p = wb + OFF_D2P;
    float* d3p = wb + OFF_D3P;
    float* w1p = wb + OFF_W1P;
    float* w2p = wb + OFF_W2P;
    float* w3p = wb + OFF_W3P;

    // ---- Pre-pass: tf32-round (and K-pad) all static GEMM operands
    launch_round_pad((const float*)D0, d0p, 1256, 5023, 5024);
    launch_round_pad((const float*)D1, d1p, 314, 1256, 1264);
    launch_round_pad((const float*)D2, d2p, 79, 314, 320);
    launch_round_pad((const float*)D3, d3p, 20, 79, 80);
    launch_round_pad((const float*)W1, w1p, 1, 18432, 18432);
    launch_round_pad((const float*)W2, w2p, 1, 73728, 73728);
    launch_round_pad((const float*)W3, w3p, 1, 294912, 294912);

    // ---- Block 0: fused spiral conv, h0 (5024,256,32) tf32-rounded
    conv0_kernel<<<(5024 * 256) / 8, 256>>>((const float*)x, (const int*)idx0,
                                            (const float*)W0, (const float*)b0, ab);
    // y0 = D0p @ h0 : (1256 x 5024) @ (5024 x 8192)
    gemm_big(1256, 256 * 32, 5024, d0p, ab, yb, nullptr, 0);

    // ---- Block 1: fused gather+conv, then pool
    conv_fused<32, 64, 32, 32>(1256 * 256, 64, yb, (const int*)idx1, w1p, ab,
                               (const float*)b1);
    gemm_big(314, 256 * 64, 1264, d1p, ab, yb, nullptr, 0);

    // ---- Block 2
    conv_fused<64, 128, 64, 32>(314 * 256, 128, yb, (const int*)idx2, w2p, ab,
                                (const float*)b2);
    gemm_m32(79, 256 * 128, 320, d2p, ab, yb, nullptr, 0);

    // ---- Block 3
    conv_fused<128, 128, 64, 32>(79 * 256, 256, yb, (const int*)idx3, w3p, ab,
                                 (const float*)b3);
    gemm_m32(20, 256 * 256, 80, d3p, ab, yb, nullptr, 0);

    // ---- Final FC: (256 x 5120) @ (5120 x 128), fp32
    fc_kernel<<<256, 128>>>(yb, (const float*)Wfc, (const float*)bfc, out);
}

// round 11
// speedup vs baseline: 4.6850x; 1.0449x over previous
#include <cuda_runtime.h>
#include <cuda_bf16.h>
#include <cstdint>

#define L_SP 9
#define BATCH 256
// Ns = 5023, 1256, 314, 79, 20 ; Cs = 3, 32, 64, 128, 256 ; latent = 128

// ---------------------------------------------------------------------------
// Scratch (device globals; no allocation allowed)
// ---------------------------------------------------------------------------
__device__ float a_buf[41156608];   // conv outputs h_i (5024*8192 for padded h0)
__device__ float y_buf[10289152];   // pooled outputs y_i   (max 1256*256*32)
__device__ float w_buf[7126336];    // tf32-rounded, K-padded D0..D3, W1..W3

// w_buf offsets (floats) — K padded to multiples of 32
#define OFF_D0P 0          // 1256 x 5024
#define OFF_D1P 6310144    // 314 x 1280
#define OFF_D2P 6712064    // 79 x 320
#define OFF_D3P 6737344    // 20 x 96
#define OFF_W1P 6739264    // 288 x 64
#define OFF_W2P 6757696    // 576 x 128
#define OFF_W3P 6831424    // 1152 x 256

__device__ __forceinline__ float f2tf32(float f) {
    uint32_t r;
    asm("cvt.rna.tf32.f32 %0, %1;" : "=r"(r) : "f"(f));
    return __uint_as_float(r);
}
__device__ __forceinline__ void cpa16(uint32_t dst, const void* src, int sz) {
    asm volatile("cp.async.cg.shared.global [%0], [%1], 16, %2;"
                 :: "r"(dst), "l"(src), "r"(sz));
}
#define CP_COMMIT() asm volatile("cp.async.commit_group;" ::: "memory")
#define CP_WAIT1()  asm volatile("cp.async.wait_group 1;" ::: "memory")

#define BKT 32  // k-tile depth per pipeline stage (4 x k8 MMA steps)
#define SA  36  // A smem row stride (BKT + 4); lane->bank (4g+tig), conflict-free

// ===========================================================================
// MMA mainloop body shared by both GEMMs. 4 k8-steps per stage.
// ===========================================================================
#define MMA_TILE_COMPUTE(Af, Bf, s, BM, SB)                                     \
    {                                                                           \
        const int aBase = (s) * (BM) * SA + (wm0 + g) * SA;                     \
        const int bBase = (s) * BKT * (SB) + wn0 + g;                           \
        _Pragma("unroll")                                                       \
        for (int kt = 0; kt < 4; kt++) {                                        \
            uint32_t af[MT][4], bfr[NT][2];                                     \
            _Pragma("unroll")                                                   \
            for (int mt = 0; mt < MT; mt++) {                                   \
                int a0 = aBase + mt * 16 * SA + kt * 8 + tig;                   \
                af[mt][0] = __float_as_uint(Af[a0]);                            \
                af[mt][1] = __float_as_uint(Af[a0 + 8 * SA]);                   \
                af[mt][2] = __float_as_uint(Af[a0 + 4]);                        \
                af[mt][3] = __float_as_uint(Af[a0 + 8 * SA + 4]);               \
            }                                                                   \
            _Pragma("unroll")                                                   \
            for (int nt = 0; nt < NT; nt++) {                                   \
                int b0i = bBase + (kt * 8 + tig) * (SB) + nt * 8;               \
                bfr[nt][0] = __float_as_uint(Bf[b0i]);                          \
                bfr[nt][1] = __float_as_uint(Bf[b0i + 4 * (SB)]);               \
            }                                                                   \
            _Pragma("unroll")                                                   \
            for (int mt = 0; mt < MT; mt++)                                     \
                _Pragma("unroll")                                               \
                for (int nt = 0; nt < NT; nt++) {                               \
                    asm volatile(                                               \
                        "mma.sync.aligned.m16n8k8.row.col.f32.tf32.tf32.f32 "   \
                        "{%0,%1,%2,%3}, {%4,%5,%6,%7}, {%8,%9}, {%0,%1,%2,%3};" \
                        : "+f"(acc[mt][nt][0]), "+f"(acc[mt][nt][1]),           \
                          "+f"(acc[mt][nt][2]), "+f"(acc[mt][nt][3])            \
                        : "r"(af[mt][0]), "r"(af[mt][1]),                       \
                          "r"(af[mt][2]), "r"(af[mt][3]),                       \
                          "r"(bfr[nt][0]), "r"(bfr[nt][1]));                    \
                }                                                               \
        }                                                                       \
    }

// ---------------------------------------------------------------------------
// tf32 GEMM, 3-stage cp.async, dynamic smem, BK=32.
// C = round_tf32(act(A(MxK) * B(KxN) + bias))
// K % 32 == 0, N % BN == 0, operands tf32-rounded, rows 16B-aligned. M free.
// ---------------------------------------------------------------------------
template <int BM, int BN, int WM, int WN>
__global__ __launch_bounds__(256) void gemm_tca(
    int M, int N, int K,
    const float* __restrict__ A, const float* __restrict__ B,
    float* __restrict__ C, const float* __restrict__ bias, int act)
{
    constexpr int SB = BN + 8;
    constexpr int NWN = BN / WN;
    constexpr int NWM = BM / WM;
    static_assert(NWM * NWN == 8, "8 warps");
    constexpr int MT = WM / 16;
    constexpr int NT = WN / 8;

    extern __shared__ float smem[];
    float* Af = smem;                      // 3 * BM * SA
    float* Bf = smem + 3 * BM * SA;        // 3 * BKT * SB

    const int tid = threadIdx.x;
    const int warp = tid >> 5;
    const int lane = tid & 31;
    const int g = lane >> 2;
    const int tig = lane & 3;
    const int wn0 = (warp % NWN) * WN;
    const int wm0 = (warp / NWN) * WM;
    const int row0 = blockIdx.y * BM;
    const int col0 = blockIdx.x * BN;

    const uint32_t sA = (uint32_t)__cvta_generic_to_shared(Af);
    const uint32_t sB = (uint32_t)__cvta_generic_to_shared(Bf);

    constexpr int KV = BKT / 4;              // 8 float4 per A row
    constexpr int AF4 = BM * KV;
    constexpr int A_IT = (AF4 + 255) / 256;
    constexpr int NQ = BN / 4;
    constexpr int BF4 = BKT * NQ;
    constexpr int B_IT = (BF4 + 255) / 256;

    float acc[MT][NT][4];
#pragma unroll
    for (int i = 0; i < MT; i++)
#pragma unroll
        for (int j = 0; j < NT; j++)
#pragma unroll
            for (int v = 0; v < 4; v++) acc[i][j][v] = 0.f;

    const int ktiles = K / BKT;

    auto issue = [&](int t, int s) {
#pragma unroll
        for (int i = 0; i < A_IT; i++) {
            int lin = tid + i * 256;
            if ((AF4 % 256 == 0) || (lin < AF4)) {
                int m = lin / KV;
                int kq = lin % KV;
                int gm = row0 + m;
                int sz = (gm < M) ? 16 : 0;
                int gmc = (gm < M) ? gm : (M - 1);
                const float* src = A + (long long)gmc * K + t * BKT + kq * 4;
                uint32_t dst = sA + (((s * BM + m) * SA) + kq * 4) * 4u;
                cpa16(dst, src, sz);
            }
        }
#pragma unroll
        for (int i = 0; i < B_IT; i++) {
            int lin = tid + i * 256;
            if ((BF4 % 256 == 0) || (lin < BF4)) {
                int k = lin / NQ;
                int n4 = lin % NQ;
                const float* src = B + (long long)(t * BKT + k) * N + col0 + n4 * 4;
                uint32_t dst = sB + (((s * BKT + k) * SB) + n4 * 4) * 4u;
                cpa16(dst, src, 16);
            }
        }
    };

    issue(0, 0); CP_COMMIT();
    issue(1, 1); CP_COMMIT();

    int s = 0;
    for (int t = 0; t < ktiles; t++) {
        CP_WAIT1();
        __syncthreads();
        MMA_TILE_COMPUTE(Af, Bf, s, BM, SB);
        if (t + 2 < ktiles) {
            int s2 = s + 2; if (s2 >= 3) s2 -= 3;
            issue(t + 2, s2);
        }
        CP_COMMIT();   // always commit (empty at tail) so wait_group 1 drains t
        if (++s == 3) s = 0;
    }

#pragma unroll
    for (int mt = 0; mt < MT; mt++) {
#pragma unroll
        for (int nt = 0; nt < NT; nt++) {
            int gn = col0 + wn0 + nt * 8 + 2 * tig;
            float bv0 = bias ? bias[gn] : 0.f;
            float bv1 = bias ? bias[gn + 1] : 0.f;
            int r0 = row0 + wm0 + mt * 16 + g;
            int r1 = r0 + 8;
            if (r0 < M) {
                float v0 = acc[mt][nt][0] + bv0;
                float v1 = acc[mt][nt][1] + bv1;
                if (act) { v0 = (v0 > 0.f) ? v0 : expm1f(v0);
                           v1 = (v1 > 0.f) ? v1 : expm1f(v1); }
                *(float2*)&C[(long long)r0 * N + gn] =
                    make_float2(f2tf32(v0), f2tf32(v1));
            }
            if (r1 < M) {
                float v0 = acc[mt][nt][2] + bv0;
                float v1 = acc[mt][nt][3] + bv1;
                if (act) { v0 = (v0 > 0.f) ? v0 : expm1f(v0);
                           v1 = (v1 > 0.f) ? v1 : expm1f(v1); }
                *(float2*)&C[(long long)r1 * N + gn] =
                    make_float2(f2tf32(v0), f2tf32(v1));
            }
        }
    }
}

// ---------------------------------------------------------------------------
// Fused gather + conv GEMM (BK=32). A is the IMPLICIT spiral-gathered matrix:
//   A[row=(n*256+b)][k=l*C+c] = Y[(idx[n*9+l]*256 + b)*C + c]
// BM=128 -> one node n per block. h = round_tf32(elu(A@W + bias)).
// K = 9*C (mult of 32 for C=32/64/128). M % 128 == 0.
// ---------------------------------------------------------------------------
template <int C, int BN, int WM, int WN>
__global__ __launch_bounds__(256) void gemm_conv(
    int M, int N,
    const float* __restrict__ Y, const int* __restrict__ idx,
    const float* __restrict__ W, float* __restrict__ H,
    const float* __restrict__ bias)
{
    constexpr int BM = 128;
    constexpr int K = 9 * C;
    constexpr int SB = BN + 8;
    constexpr int NWN = BN / WN;
    constexpr int NWM = BM / WM;
    static_assert(NWM * NWN == 8, "8 warps");
    constexpr int MT = WM / 16;
    constexpr int NT = WN / 8;

    extern __shared__ float smem[];
    float* Af = smem;
    float* Bf = smem + 3 * BM * SA;
    __shared__ int idx_s[L_SP];

    const int tid = threadIdx.x;
    const int warp = tid >> 5;
    const int lane = tid & 31;
    const int g = lane >> 2;
    const int tig = lane & 3;
    const int wn0 = (warp % NWN) * WN;
    const int wm0 = (warp / NWN) * WM;
    const int row0 = blockIdx.y * BM;
    const int col0 = blockIdx.x * BN;
    const int n = row0 >> 8;
    const int b0 = row0 & 255;

    if (tid < L_SP) idx_s[tid] = idx[n * L_SP + tid];
    __syncthreads();

    const uint32_t sA = (uint32_t)__cvta_generic_to_shared(Af);
    const uint32_t sB = (uint32_t)__cvta_generic_to_shared(Bf);

    constexpr int KV = BKT / 4;
    constexpr int AF4 = BM * KV;             // 1024
    constexpr int A_IT = AF4 / 256;          // 4
    constexpr int NQ = BN / 4;
    constexpr int BF4 = BKT * NQ;
    constexpr int B_IT = (BF4 + 255) / 256;

    float acc[MT][NT][4];
#pragma unroll
    for (int i = 0; i < MT; i++)
#pragma unroll
        for (int j = 0; j < NT; j++)
#pragma unroll
            for (int v = 0; v < 4; v++) acc[i][j][v] = 0.f;

    constexpr int ktiles = K / BKT;

    auto issue = [&](int t, int s) {
#pragma unroll
        for (int i = 0; i < A_IT; i++) {
            int lin = tid + i * 256;
            int m = lin / KV;
            int kq = lin % KV;
            int col = t * BKT + kq * 4;      // 4-float chunk never crosses C-block
            int l = col / C;                  // compile-time C -> shifts
            int c = col % C;
            int node = idx_s[l];
            const float* src = Y + ((long long)(node * 256 + b0 + m)) * C + c;
            uint32_t dst = sA + (((s * BM + m) * SA) + kq * 4) * 4u;
            cpa16(dst, src, 16);
        }
#pragma unroll
        for (int i = 0; i < B_IT; i++) {
            int lin = tid + i * 256;
            if ((BF4 % 256 == 0) || (lin < BF4)) {
                int k = lin / NQ;
                int n4 = lin % NQ;
                const float* src = W + (long long)(t * BKT + k) * N + col0 + n4 * 4;
                uint32_t dst = sB + (((s * BKT + k) * SB) + n4 * 4) * 4u;
                cpa16(dst, src, 16);
            }
        }
    };

    issue(0, 0); CP_COMMIT();
    issue(1, 1); CP_COMMIT();

    int s = 0;
    for (int t = 0; t < ktiles; t++) {
        CP_WAIT1();
        __syncthreads();
        MMA_TILE_COMPUTE(Af, Bf, s, BM, SB);
        if (t + 2 < ktiles) {
            int s2 = s + 2; if (s2 >= 3) s2 -= 3;
            issue(t + 2, s2);
        }
        CP_COMMIT();
        if (++s == 3) s = 0;
    }

#pragma unroll
    for (int mt = 0; mt < MT; mt++) {
#pragma unroll
        for (int nt = 0; nt < NT; nt++) {
            int gn = col0 + wn0 + nt * 8 + 2 * tig;
            float bv0 = bias[gn];
            float bv1 = bias[gn + 1];
            int r0 = row0 + wm0 + mt * 16 + g;
            int r1 = r0 + 8;
            {
                float v0 = acc[mt][nt][0] + bv0;
                float v1 = acc[mt][nt][1] + bv1;
                v0 = (v0 > 0.f) ? v0 : expm1f(v0);
                v1 = (v1 > 0.f) ? v1 : expm1f(v1);
                *(float2*)&H[(long long)r0 * N + gn] =
                    make_float2(f2tf32(v0), f2tf32(v1));
            }
            {
                float v0 = acc[mt][nt][2] + bv0;
                float v1 = acc[mt][nt][3] + bv1;
                v0 = (v0 > 0.f) ? v0 : expm1f(v0);
                v1 = (v1 > 0.f) ? v1 : expm1f(v1);
                *(float2*)&H[(long long)r1 * N + gn] =
                    make_float2(f2tf32(v0), f2tf32(v1));
            }
        }
    }
}

// ---------------------------------------------------------------------------
// Pre-pass: round src to tf32 and zero-pad rows from kin to kout columns.
// ---------------------------------------------------------------------------
__global__ __launch_bounds__(256) void round_pad_kernel(
    const float* __restrict__ src, float* __restrict__ dst,
    int kin, int kout, long long total)
{
    long long i = (long long)blockIdx.x * blockDim.x + threadIdx.x;
    if (i >= total) return;
    int k = (int)(i % kout);
    long long r = i / kout;
    dst[i] = (k < kin) ? f2tf32(src[r * kin + k]) : 0.f;
}

// ---------------------------------------------------------------------------
// Stage-0 fused spiral conv (tf32-rounded h0, zero row at n=5023).
// ---------------------------------------------------------------------------
__global__ __launch_bounds__(256) void conv0_kernel(
    const float* __restrict__ x, const int* __restrict__ idx,
    const float* __restrict__ W, const float* __restrict__ bias,
    float* __restrict__ h)
{
    __shared__ float Ws[27 * 32];
    __shared__ float bs[32];
    const int tid = threadIdx.x;
    for (int i = tid; i < 27 * 32; i += 256) Ws[i] = W[i];
    if (tid < 32) bs[tid] = bias[tid];
    __syncthreads();

    const int warp = tid >> 5, lane = tid & 31;
    const long long row = (long long)blockIdx.x * 8 + warp;
    const int n = (int)(row >> 8);
    const int b = (int)(row & 255);

    if (n >= 5023) { h[row * 32 + lane] = 0.f; return; }

    float gval = 0.f;
    if (lane < 27) {
        int l = lane / 3, c = lane - l * 3;
        int node = idx[n * L_SP + l];
        gval = x[(long long)b * (5023 * 3) + node * 3 + c];
    }
    float acc = bs[lane];
#pragma unroll
    for (int k = 0; k < 27; k++) {
        float a = __shfl_sync(0xffffffffu, gval, k);
        acc += a * Ws[k * 32 + lane];
    }
    acc = (acc > 0.f) ? acc : expm1f(acc);
    h[row * 32 + lane] = f2tf32(acc);
}

// ---------------------------------------------------------------------------
// Final FC (fp32)
// ---------------------------------------------------------------------------
__global__ __launch_bounds__(128) void fc_kernel(
    const float* __restrict__ h, const float* __restrict__ W,
    const float* __restrict__ bias, float* __restrict__ out)
{
    __shared__ float s[5120];
    const int b = blockIdx.x;
    for (int k = threadIdx.x; k < 5120; k += 128) {
        int n = k >> 8, c = k & 255;
        s[k] = h[n * 65536 + b * 256 + c];
    }
    __syncthreads();
    float acc = bias[threadIdx.x];
#pragma unroll 8
    for (int k = 0; k < 5120; k++)
        acc += s[k] * W[k * 128 + threadIdx.x];
    out[b * 128 + threadIdx.x] = acc;
}

// ---------------------------------------------------------------------------
// Launch helpers
// ---------------------------------------------------------------------------
static inline int smem_bytes(int BM, int BN) {
    return (3 * BM * SA + 3 * BKT * (BN + 8)) * 4;
}

static inline void gemm_big(int M, int N, int K, const float* A, const float* B,
                            float* C, const float* bias, int act)
{
    int sm = smem_bytes(128, 128);
    cudaFuncSetAttribute(gemm_tca<128, 128, 64, 32>,
                         cudaFuncAttributeMaxDynamicSharedMemorySize, sm);
    dim3 grid(N / 128, (M + 127) / 128);
    gemm_tca<128, 128, 64, 32><<<grid, 256, sm>>>(M, N, K, A, B, C, bias, act);
}
static inline void gemm_m32(int M, int N, int K, const float* A, const float* B,
                            float* C, const float* bias, int act)
{
    int sm = smem_bytes(32, 128);
    cudaFuncSetAttribute(gemm_tca<32, 128, 16, 32>,
                         cudaFuncAttributeMaxDynamicSharedMemorySize, sm);
    dim3 grid(N / 128, (M + 31) / 32);
    gemm_tca<32, 128, 16, 32><<<grid, 256, sm>>>(M, N, K, A, B, C, bias, act);
}
template <int C, int BN, int WM, int WN>
static inline void conv_fused(int M, int N, const float* Y, const int* idx,
                              const float* W, float* H, const float* bias)
{
    int sm = smem_bytes(128, BN);
    cudaFuncSetAttribute(gemm_conv<C, BN, WM, WN>,
                         cudaFuncAttributeMaxDynamicSharedMemorySize, sm);
    dim3 grid(N / BN, M / 128);
    gemm_conv<C, BN, WM, WN><<<grid, 256, sm>>>(M, N, Y, idx, W, H, bias);
}
static inline void launch_round_pad(const float* src, float* dst, int rows, int kin, int kout)
{
    long long total = (long long)rows * kout;
    int blocks = (int)((total + 255) / 256);
    round_pad_kernel<<<blocks, 256>>>(src, dst, kin, kout, total);
}

// ---------------------------------------------------------------------------
// kernel_launch — inputs bound BY ELEMENT COUNT.
// Launch order puts the D0 GEMM at position 6 so ncu (-s 5 -c 1) profiles it.
// ---------------------------------------------------------------------------
extern "C" void kernel_launch(void* const* d_in, const int* in_sizes, int n_in,
                              void* d_out, int out_size)
{
    const void* x = 0; const void* idx0 = 0; const void* idx1 = 0;
    const void* idx2 = 0; const void* idx3 = 0;
    const void* D0 = 0; const void* D1 = 0; const void* D2 = 0; const void* D3 = 0;
    const void* W0 = 0; const void* b0 = 0; const void* W1 = 0; const void* b1 = 0;
    const void* W2 = 0; const void* b2 = 0; const void* W3 = 0; const void* b3 = 0;
    const void* Wfc = 0; const void* bfc = 0;

    for (int i = 0; i < n_in; i++) {
        const void* p = d_in[i];
        switch (in_sizes[i]) {
            case 3857664: x    = p; break;   // 256*5023*3
            case 45207:   idx0 = p; break;   // 5023*9
            case 11304:   idx1 = p; break;   // 1256*9
            case 2826:    idx2 = p; break;   // 314*9
            case 711:     idx3 = p; break;   // 79*9
            case 6308888: D0   = p; break;   // 1256*5023
            case 394384:  D1   = p; break;   // 314*1256
            case 24806:   D2   = p; break;   // 79*314
            case 1580:    D3   = p; break;   // 20*79
            case 864:     W0   = p; break;   // 27*32
            case 32:      b0   = p; break;
            case 18432:   W1   = p; break;   // 288*64
            case 64:      b1   = p; break;
            case 73728:   W2   = p; break;   // 576*128
            case 294912:  W3   = p; break;   // 1152*256
            case 256:     b3   = p; break;
            case 655360:  Wfc  = p; break;   // 5120*128
            case 128:     if (!b2) b2 = p; else bfc = p; break;
            default: break;
        }
    }

    float* out = (float*)d_out;
    float* ab; cudaGetSymbolAddress((void**)&ab, a_buf);
    float* yb; cudaGetSymbolAddress((void**)&yb, y_buf);
    float* wb; cudaGetSymbolAddress((void**)&wb, w_buf);

    float* d0p = wb + OFF_D0P;
    float* d1p = wb + OFF_D1P;
    float* d2p = wb + OFF_D2P;
    float* d3p = wb + OFF_D3P;
    float* w1p = wb + OFF_W1P;
    float* w2p = wb + OFF_W2P;
    float* w3p = wb + OFF_W3P;

    // Launches 1-5: D round_pads + conv0 (so launch 6 = D0 GEMM, ncu target)
    launch_round_pad((const float*)D0, d0p, 1256, 5023, 5024);   // 1
    launch_round_pad((const float*)D1, d1p, 314, 1256, 1280);    // 2
    launch_round_pad((const float*)D2, d2p, 79, 314, 320);       // 3
    launch_round_pad((const float*)D3, d3p, 20, 79, 96);         // 4
    conv0_kernel<<<(5024 * 256) / 8, 256>>>((const float*)x, (const int*)idx0,
                                            (const float*)W0, (const float*)b0, ab); // 5

    // Launch 6: y0 = D0p @ h0 : (1256 x 5024) @ (5024 x 8192)  << PROFILED
    gemm_big(1256, 256 * 32, 5024, d0p, ab, yb, nullptr, 0);

    // W round_pads (needed from conv1 onward)
    launch_round_pad((const float*)W1, w1p, 1, 18432, 18432);
    launch_round_pad((const float*)W2, w2p, 1, 73728, 73728);
    launch_round_pad((const float*)W3, w3p, 1, 294912, 294912);

    // ---- Block 1: fused gather+conv, then pool
    conv_fused<32, 64, 32, 32>(1256 * 256, 64, yb, (const int*)idx1, w1p, ab,
                               (const float*)b1);
    gemm_big(314, 256 * 64, 1280, d1p, ab, yb, nullptr, 0);

    // ---- Block 2
    conv_fused<64, 128, 64, 32>(314 * 256, 128, yb, (const int*)idx2, w2p, ab,
                                (const float*)b2);
    gemm_m32(79, 256 * 128, 320, d2p, ab, yb, nullptr, 0);

    // ---- Block 3
    conv_fused<128, 128, 64, 32>(79 * 256, 256, yb, (const int*)idx3, w3p, ab,
                                 (const float*)b3);
    gemm_m32(20, 256 * 256, 96, d3p, ab, yb, nullptr, 0);

    // ---- Final FC: (256 x 5120) @ (5120 x 128), fp32
    fc_kernel<<<256, 128>>>(yb, (const float*)Wfc, (const float*)bfc, out);
}